// round 12
// baseline (speedup 1.0000x reference)
#include <cuda_runtime.h>
#include <cuda_fp16.h>
#include <math.h>
#include <stdint.h>

#define BB 2
#define LL 401
#define DD 128
#define NBI (BB*LL)   // 802
#define HP 68         // smem row pitch in half2 (136 halfs, 272 B)

__device__ __half g_tmp_h[(size_t)NBI * DD * DD];             // 26.3 MB tmp[b,i,k,e] fp16
__device__ __align__(16) __half2 g_WbT[(size_t)DD * DD * 64]; // 4 MB: [k][e][d-pairs]
__device__ __align__(16) __half  g_x_h[(size_t)BB * 512 * DD];// padded fp16 x: [b][512][128]
__device__ __align__(16) __half  g_W1p[(size_t)DD * DD];      // W1[e][d]*ln_g[d] fp16
__device__ float  g_b1p[DD];                                  // b1 + ln_b @ W1^T
__device__ float  g_C[(size_t)BB * LL * LL];

// ---------------------------------------------------------------------------
__device__ __forceinline__ void mma_f16(float c[4],
                                        uint32_t a0, uint32_t a1, uint32_t a2, uint32_t a3,
                                        uint32_t b0, uint32_t b1)
{
    asm volatile(
        "mma.sync.aligned.m16n8k16.row.col.f32.f16.f16.f32 "
        "{%0,%1,%2,%3}, {%4,%5,%6,%7}, {%8,%9}, {%0,%1,%2,%3};"
        : "+f"(c[0]), "+f"(c[1]), "+f"(c[2]), "+f"(c[3])
        : "r"(a0), "r"(a1), "r"(a2), "r"(a3), "r"(b0), "r"(b1));
}
__device__ __forceinline__ void ldsm4(uint32_t r[4], uint32_t addr)
{
    asm volatile("ldmatrix.sync.aligned.m8n8.x4.shared.b16 {%0,%1,%2,%3}, [%4];"
                 : "=r"(r[0]), "=r"(r[1]), "=r"(r[2]), "=r"(r[3]) : "r"(addr));
}
__device__ __forceinline__ void barp(int id)
{
    asm volatile("bar.sync %0, 64;" :: "r"(id) : "memory");
}

// Branch-free GELU without the 0.5 (folded into w2): v*(1+erf(v/sqrt2)).
// A&S 7.1.26 erf, rcp.approx + expf (round-10 proven-best variant).
__device__ __forceinline__ float gelu2x(float v)
{
    float z   = v * 0.70710678118654752f;
    float az  = fabsf(z);
    float den = fmaf(0.3275911f, az, 1.0f);
    float t;
    asm("rcp.approx.f32 %0, %1;" : "=f"(t) : "f"(den));
    float e = __expf(-z * z);
    float p = fmaf(1.061405429f, t, -1.453152027f);
    p = fmaf(p, t, 1.421413741f);
    p = fmaf(p, t, -0.284496736f);
    p = fmaf(p, t, 0.254829592f);
    p = p * t;
    float erfa = fmaf(-p, e, 1.0f);
    float erfv = copysignf(erfa, z);
    return v * (1.0f + erfv);
}

// ---------------------------------------------------------------------------
// Kernel 0: one-time transpose W_bil[k][d][e] (fp32) -> g_WbT[k][e][d-pairs] (fp16)
// ---------------------------------------------------------------------------
__global__ __launch_bounds__(256, 2) void k0_transpose(const float* __restrict__ Wb)
{
    __shared__ __half Sg[128 * 130];
    const int k   = blockIdx.x;
    const int tid = threadIdx.x;
    const float* Wk = Wb + (size_t)k * DD * DD;

    #pragma unroll
    for (int s = 0; s < 16; ++s) {
        int v = tid + (s << 8);
        int d = v >> 5, e4 = (v & 31) << 2;
        float4 w = *(const float4*)&Wk[d * DD + e4];
        __half2* dst = (__half2*)&Sg[d * 130 + e4];
        dst[0] = __floats2half2_rn(w.x, w.y);
        dst[1] = __floats2half2_rn(w.z, w.w);
    }
    __syncthreads();

    __half2* out = g_WbT + (size_t)k * (DD * 64);
    #pragma unroll
    for (int s = 0; s < 32; ++s) {
        int v = tid + (s << 8);
        int e = v >> 6, d2 = v & 63;
        __half lo = Sg[(2 * d2) * 130 + e];
        __half hi = Sg[(2 * d2 + 1) * 130 + e];
        out[e * 64 + d2] = __halves2half2(lo, hi);
    }
}

// ---------------------------------------------------------------------------
// Kernel 0x: convert x (fp32) -> g_x_h fp16, padded to 512 rows per b.
// ---------------------------------------------------------------------------
__global__ __launch_bounds__(256) void k0x_convert(const float* __restrict__ x)
{
    int idx = blockIdx.x * 256 + threadIdx.x;
    if (idx >= BB * 512 * 64) return;
    int b   = idx >> 15;
    int rem = idx & 32767;
    int r   = rem >> 6, c2 = rem & 63;
    __half2 h;
    if (r < LL) {
        const float* sp = &x[((size_t)(b * LL + r)) * DD + c2 * 2];
        h = __floats2half2_rn(sp[0], sp[1]);
    } else {
        h = __floats2half2_rn(0.f, 0.f);
    }
    *(__half2*)&g_x_h[((size_t)(b * 512 + r)) * DD + c2 * 2] = h;
}

// ---------------------------------------------------------------------------
// Kernel 0w: fold LN affine into W1 (fp32 precompute, one-time):
//   g_W1p[e][d] = fp16(W1[e][d] * ln_g[d]);  g_b1p[e] = b1[e] + sum_d ln_b[d]*W1[e][d]
// ---------------------------------------------------------------------------
__global__ __launch_bounds__(128) void k0w_fold(const float* __restrict__ W1,
                                                const float* __restrict__ ln_g,
                                                const float* __restrict__ ln_b,
                                                const float* __restrict__ b1)
{
    int e = threadIdx.x;
    float acc = b1[e];
    #pragma unroll 4
    for (int d = 0; d < DD; ++d) {
        float w = W1[e * DD + d];
        acc = fmaf(ln_b[d], w, acc);
        g_W1p[e * DD + d] = __float2half_rn(w * ln_g[d]);
    }
    g_b1p[e] = acc;
}

// ---------------------------------------------------------------------------
// Kernel 1 (fp16 mma + ldmatrix): tmp[bi][k][e] = sum_d x[bi][d]*W_bil[k][d][e]
// ---------------------------------------------------------------------------
#define K1_XS 0u
#define K1_WT 34816u
#define K1_SMEM 69632u

__global__ __launch_bounds__(256, 2) void k1_tmp()
{
    extern __shared__ char smc[];
    __half2* Xs = (__half2*)(smc + K1_XS);
    __half2* Wt = (__half2*)(smc + K1_WT);

    const int k   = blockIdx.x;
    const int bi0 = blockIdx.y * 128;
    const int tid = threadIdx.x, tx = tid & 31, wid = tid >> 5;
    const int wj  = wid & 3, wk = wid >> 2;
    const int g   = tx >> 2, c = tx & 3;
    const int arow = wj * 32, bcol = wk * 64;

    const __half2* Wsrc = g_WbT + (size_t)k * (DD * 64);
    #pragma unroll
    for (int s = 0; s < 8; ++s) {
        int v = tid + (s << 8);
        int row = v >> 4, u = (v & 15) << 2;
        uint4 t = *(const uint4*)&Wsrc[row * 64 + u];
        *(uint4*)&Wt[row * HP + u] = t;
    }
    #pragma unroll
    for (int s = 0; s < 8; ++s) {
        int v = tid + (s << 8);
        int row = v >> 4, seg = v & 15;
        int bi = bi0 + row;
        int bb_ = (bi >= LL) ? 1 : 0;
        int r = bi - bb_ * LL;
        uint4 t = *(const uint4*)&g_x_h[((size_t)(bb_ * 512 + r)) * DD + seg * 8];
        *(uint4*)((char*)Xs + row * 272 + seg * 16) = t;
    }
    __syncthreads();

    const uint32_t sb  = (uint32_t)__cvta_generic_to_shared(smc);
    const uint32_t sbX = sb + K1_XS, sbW = sb + K1_WT;

    uint32_t aAddr[2], bOff[4];
    #pragma unroll
    for (int mf = 0; mf < 2; ++mf) {
        int row = arow + mf * 16 + (tx & 7) + ((tx & 8) ? 8 : 0);
        aAddr[mf] = sbX + row * 272 + ((tx & 16) ? 16 : 0);
    }
    #pragma unroll
    for (int p = 0; p < 4; ++p) {
        int row = bcol + p * 16 + (tx & 7) + ((tx & 16) ? 8 : 0);
        bOff[p] = row * 272 + ((tx & 8) ? 16 : 0);
    }

    float acc[2][8][4];
    #pragma unroll
    for (int mf = 0; mf < 2; ++mf)
        #pragma unroll
        for (int nt = 0; nt < 8; ++nt)
            #pragma unroll
            for (int u = 0; u < 4; ++u) acc[mf][nt][u] = 0.0f;

    #pragma unroll
    for (int kc = 0; kc < 8; ++kc) {
        int ko = kc * 32;
        uint32_t a0[4], a1[4];
        ldsm4(a0, aAddr[0] + ko);
        ldsm4(a1, aAddr[1] + ko);
        #pragma unroll
        for (int p = 0; p < 4; ++p) {
            uint32_t bb[4];
            ldsm4(bb, sbW + bOff[p] + ko);
            mma_f16(acc[0][2 * p],     a0[0], a0[1], a0[2], a0[3], bb[0], bb[1]);
            mma_f16(acc[1][2 * p],     a1[0], a1[1], a1[2], a1[3], bb[0], bb[1]);
            mma_f16(acc[0][2 * p + 1], a0[0], a0[1], a0[2], a0[3], bb[2], bb[3]);
            mma_f16(acc[1][2 * p + 1], a1[0], a1[1], a1[2], a1[3], bb[2], bb[3]);
        }
    }

    #pragma unroll
    for (int mf = 0; mf < 2; ++mf)
        #pragma unroll
        for (int nt = 0; nt < 8; ++nt) {
            int r0  = bi0 + arow + mf * 16 + g;
            int col = bcol + nt * 8 + 2 * c;
            if (r0 < NBI)
                *(__half2*)&g_tmp_h[(size_t)r0 * (DD * DD) + k * DD + col] =
                    __floats2half2_rn(acc[mf][nt][0], acc[mf][nt][1]);
            int r1 = r0 + 8;
            if (r1 < NBI)
                *(__half2*)&g_tmp_h[(size_t)r1 * (DD * DD) + k * DD + col] =
                    __floats2half2_rn(acc[mf][nt][2], acc[mf][nt][3]);
        }
}

// ---------------------------------------------------------------------------
// Kernel 2 (round-10 structure): per (b,i) CTA, warp-pair independent,
// tiles {128,128,128,32}; LN affine pre-folded into g_W1p/g_b1p.
// ---------------------------------------------------------------------------
#define K2_TS 0u
#define K2_WS 34816u
#define K2_XS 69632u
#define K2_CV 104448u        // 384 floats: bbs, b1s, w2s
#define K2_RA 107008u
#define K2_RB 109056u
#define K2_SMEM 110080u

__global__ __launch_bounds__(256, 2) void k2_fused(
    const float* __restrict__ b_bil, const float* __restrict__ w2,
    const float* __restrict__ b2)
{
    extern __shared__ char smc[];
    __half2* Ts  = (__half2*)(smc + K2_TS);
    __half2* W1s = (__half2*)(smc + K2_WS);
    __half2* Xs  = (__half2*)(smc + K2_XS);
    float* cv  = (float*)(smc + K2_CV);
    float* bbs = cv; float* b1s = cv + 128; float* w2s = cv + 256;
    float2* redA = (float2*)(smc + K2_RA);
    float*  redB = (float*) (smc + K2_RB);

    const int bi  = blockIdx.x;
    const int b   = bi / LL;
    const int tid = threadIdx.x, tx = tid & 31, wid = tid >> 5;
    const int wj  = wid & 3, wk = wid >> 2;
    const int g   = tx >> 2, c = tx & 3;
    const int arow = wj * 32, bcol = wk * 64;
    const int pt  = wk * 32 + tx;          // thread index within pair [0,64)
    const int pb  = wj + 1;                // named barrier id

    // Ts: raw fp16 copy of tmp_i.  W1s: raw fp16 copy of pre-folded W1'.
    const __half* tp = g_tmp_h + (size_t)bi * DD * DD;
    #pragma unroll
    for (int s = 0; s < 8; ++s) {
        int v = tid + (s << 8);
        int row = v >> 4, seg = (v & 15) << 3;
        uint4 tv = *(const uint4*)&tp[row * DD + seg];
        *(uint4*)((char*)Ts + row * 272 + seg * 2) = tv;
        uint4 wv = *(const uint4*)&g_W1p[row * DD + seg];
        *(uint4*)((char*)W1s + row * 272 + seg * 2) = wv;
    }
    if (tid < 128) {
        bbs[tid] = b_bil[tid];
        b1s[tid] = g_b1p[tid];
        w2s[tid] = 0.5f * w2[tid];   // GELU 0.5 folded
    }
    const float b2v = b2[0];
    const __half* xh = g_x_h + (size_t)b * 512 * DD;
    float* Crow = g_C + (size_t)bi * LL;

    const uint32_t sb  = (uint32_t)__cvta_generic_to_shared(smc);
    const uint32_t sbX = sb + K2_XS, sbT = sb + K2_TS, sbW = sb + K2_WS;

    uint32_t aAddr[2], bOff[4];
    #pragma unroll
    for (int mf = 0; mf < 2; ++mf) {
        int row = arow + mf * 16 + (tx & 7) + ((tx & 8) ? 8 : 0);
        aAddr[mf] = sbX + row * 272 + ((tx & 16) ? 16 : 0);
    }
    #pragma unroll
    for (int p = 0; p < 4; ++p) {
        int row = bcol + p * 16 + (tx & 7) + ((tx & 16) ? 8 : 0);
        bOff[p] = row * 272 + ((tx & 8) ? 16 : 0);
    }
    __syncthreads();   // Ts/W1s/constants visible; last CTA-wide sync

    #pragma unroll 1
    for (int t = 0; t < 4; ++t) {
        const int j0 = t * 128;
        const int mrows = (t == 3) ? 32 : 128;
        if (arow >= mrows) continue;   // whole pair skips tail together

        // ---- Pair loads its own 32 X rows (raw fp16 copy) ----
        #pragma unroll
        for (int s = 0; s < 8; ++s) {
            int u = pt + (s << 6);
            int row = arow + (u >> 4), seg = u & 15;
            uint4 tv = *(const uint4*)&xh[((size_t)(j0 + row)) * DD + seg * 8];
            *(uint4*)((char*)Xs + row * 272 + seg * 16) = tv;
        }
        barp(pb);

        // ---- Phase A: pair = X @ Ts^T ----
        float acc[2][8][4];
        #pragma unroll
        for (int mf = 0; mf < 2; ++mf)
            #pragma unroll
            for (int nt = 0; nt < 8; ++nt)
                #pragma unroll
                for (int u = 0; u < 4; ++u) acc[mf][nt][u] = 0.0f;

        #pragma unroll
        for (int kc = 0; kc < 8; ++kc) {
            int ko = kc * 32;
            uint32_t a0[4], a1[4];
            ldsm4(a0, aAddr[0] + ko);
            ldsm4(a1, aAddr[1] + ko);
            #pragma unroll
            for (int p = 0; p < 4; ++p) {
                uint32_t bb[4];
                ldsm4(bb, sbT + bOff[p] + ko);
                mma_f16(acc[0][2 * p],     a0[0], a0[1], a0[2], a0[3], bb[0], bb[1]);
                mma_f16(acc[1][2 * p],     a1[0], a1[1], a1[2], a1[3], bb[0], bb[1]);
                mma_f16(acc[0][2 * p + 1], a0[0], a0[1], a0[2], a0[3], bb[2], bb[3]);
                mma_f16(acc[1][2 * p + 1], a1[0], a1[1], a1[2], a1[3], bb[2], bb[3]);
            }
        }

        // ---- LN stats ----
        float s1[4] = {0.f, 0.f, 0.f, 0.f}, s2[4] = {0.f, 0.f, 0.f, 0.f};
        #pragma unroll
        for (int mf = 0; mf < 2; ++mf)
            #pragma unroll
            for (int nt = 0; nt < 8; ++nt) {
                int col = bcol + nt * 8 + 2 * c;
                float bb0 = bbs[col], bb1 = bbs[col + 1];
                acc[mf][nt][0] += bb0; acc[mf][nt][1] += bb1;
                acc[mf][nt][2] += bb0; acc[mf][nt][3] += bb1;
                s1[mf * 2]     += acc[mf][nt][0] + acc[mf][nt][1];
                s2[mf * 2]     += acc[mf][nt][0] * acc[mf][nt][0] + acc[mf][nt][1] * acc[mf][nt][1];
                s1[mf * 2 + 1] += acc[mf][nt][2] + acc[mf][nt][3];
                s2[mf * 2 + 1] += acc[mf][nt][2] * acc[mf][nt][2] + acc[mf][nt][3] * acc[mf][nt][3];
            }
        #pragma unroll
        for (int off = 1; off <= 2; off <<= 1)
            #pragma unroll
            for (int lr = 0; lr < 4; ++lr) {
                s1[lr] += __shfl_xor_sync(0xffffffffu, s1[lr], off);
                s2[lr] += __shfl_xor_sync(0xffffffffu, s2[lr], off);
            }
        if (c == 0) {
            #pragma unroll
            for (int lr = 0; lr < 4; ++lr) {
                int row = arow + (lr >> 1) * 16 + (lr & 1) * 8 + g;
                redA[row * 2 + wk] = make_float2(s1[lr], s2[lr]);
            }
        }
        barp(pb);

        float mu[4], rs[4];
        #pragma unroll
        for (int lr = 0; lr < 4; ++lr) {
            int row = arow + (lr >> 1) * 16 + (lr & 1) * 8 + g;
            float2 rA = redA[row * 2 + 0], rB = redA[row * 2 + 1];
            float S1 = rA.x + rB.x, S2 = rA.y + rB.y;
            mu[lr] = S1 * (1.0f / 128.0f);
            rs[lr] = rsqrtf(S2 * (1.0f / 128.0f) - mu[lr] * mu[lr] + 1e-5f);
        }
        // ---- Write H = (pair - mu)*rs (fp16) into Xs; LN affine is in W1' ----
        #pragma unroll
        for (int mf = 0; mf < 2; ++mf)
            #pragma unroll
            for (int nt = 0; nt < 8; ++nt) {
                int col = bcol + nt * 8 + 2 * c;
                int h2i = (col >> 1);
                int lr0 = mf * 2, lr1 = mf * 2 + 1;
                int r0 = arow + mf * 16 + g;
                Xs[r0 * HP + h2i] = __floats2half2_rn(
                    (acc[mf][nt][0] - mu[lr0]) * rs[lr0],
                    (acc[mf][nt][1] - mu[lr0]) * rs[lr0]);
                Xs[(r0 + 8) * HP + h2i] = __floats2half2_rn(
                    (acc[mf][nt][2] - mu[lr1]) * rs[lr1],
                    (acc[mf][nt][3] - mu[lr1]) * rs[lr1]);
            }
        barp(pb);

        // ---- Phase B: o = H @ W1'^T ----
        #pragma unroll
        for (int mf = 0; mf < 2; ++mf)
            #pragma unroll
            for (int nt = 0; nt < 8; ++nt)
                #pragma unroll
                for (int u = 0; u < 4; ++u) acc[mf][nt][u] = 0.0f;

        #pragma unroll
        for (int kc = 0; kc < 8; ++kc) {
            int ko = kc * 32;
            uint32_t a0[4], a1[4];
            ldsm4(a0, aAddr[0] + ko);
            ldsm4(a1, aAddr[1] + ko);
            #pragma unroll
            for (int p = 0; p < 4; ++p) {
                uint32_t bb[4];
                ldsm4(bb, sbW + bOff[p] + ko);
                mma_f16(acc[0][2 * p],     a0[0], a0[1], a0[2], a0[3], bb[0], bb[1]);
                mma_f16(acc[1][2 * p],     a1[0], a1[1], a1[2], a1[3], bb[0], bb[1]);
                mma_f16(acc[0][2 * p + 1], a0[0], a0[1], a0[2], a0[3], bb[2], bb[3]);
                mma_f16(acc[1][2 * p + 1], a1[0], a1[1], a1[2], a1[3], bb[2], bb[3]);
            }
        }

        // ---- Epilogue: bias (pre-folded), GELU, dot w2 ----
        float tsum[4] = {0.f, 0.f, 0.f, 0.f};
        #pragma unroll
        for (int mf = 0; mf < 2; ++mf)
            #pragma unroll
            for (int nt = 0; nt < 8; ++nt) {
                int col = bcol + nt * 8 + 2 * c;
                float c0 = b1s[col], c1 = b1s[col + 1];
                float w0 = w2s[col], w1 = w2s[col + 1];
                tsum[mf * 2]     += gelu2x(acc[mf][nt][0] + c0) * w0
                                  + gelu2x(acc[mf][nt][1] + c1) * w1;
                tsum[mf * 2 + 1] += gelu2x(acc[mf][nt][2] + c0) * w0
                                  + gelu2x(acc[mf][nt][3] + c1) * w1;
            }
        #pragma unroll
        for (int off = 1; off <= 2; off <<= 1)
            #pragma unroll
            for (int lr = 0; lr < 4; ++lr)
                tsum[lr] += __shfl_xor_sync(0xffffffffu, tsum[lr], off);
        if (c == 0) {
            #pragma unroll
            for (int lr = 0; lr < 4; ++lr) {
                int row = arow + (lr >> 1) * 16 + (lr & 1) * 8 + g;
                redB[row * 2 + wk] = tsum[lr];
            }
        }
        barp(pb);

        // ---- C write ----
        if (wk == 0) {
            int row = arow + tx;
            int j = j0 + row;
            if (row < mrows && j < LL)
                Crow[j] = redB[row * 2] + redB[row * 2 + 1] + b2v;
        }
    }
}

// ---------------------------------------------------------------------------
// Kernel 3: out[b,i,j] = 0.5*(C[b,i,j] + C[b,j,i]) with smem tile transpose.
// ---------------------------------------------------------------------------
__global__ __launch_bounds__(256) void k3_sym(float* __restrict__ out)
{
    __shared__ float tA[32][33];
    __shared__ float tB[32][33];
    const int b  = blockIdx.z;
    const int i0 = blockIdx.y * 32, j0 = blockIdx.x * 32;
    const int tx = threadIdx.x & 31, ty = threadIdx.x >> 5;
    const float* Cb = g_C + (size_t)b * LL * LL;

    #pragma unroll
    for (int r = 0; r < 4; ++r) {
        int row = ty + r * 8;
        int gi = i0 + row, gj = j0 + tx;
        tA[row][tx] = (gi < LL && gj < LL) ? Cb[gi * LL + gj] : 0.f;
        int hi = j0 + row, hj = i0 + tx;
        tB[row][tx] = (hi < LL && hj < LL) ? Cb[hi * LL + hj] : 0.f;
    }
    __syncthreads();

    float* Ob = out + (size_t)b * LL * LL;
    #pragma unroll
    for (int r = 0; r < 4; ++r) {
        int row = ty + r * 8;
        int gi = i0 + row, gj = j0 + tx;
        if (gi < LL && gj < LL)
            Ob[gi * LL + gj] = 0.5f * (tA[row][tx] + tB[tx][row]);
    }
}

// ---------------------------------------------------------------------------
extern "C" void kernel_launch(void* const* d_in, const int* in_sizes, int n_in,
                              void* d_out, int out_size)
{
    (void)in_sizes; (void)n_in; (void)out_size;
    const float* x     = (const float*)d_in[0];
    const float* W_bil = (const float*)d_in[1];
    const float* b_bil = (const float*)d_in[2];
    const float* ln_g  = (const float*)d_in[3];
    const float* ln_b  = (const float*)d_in[4];
    const float* W1    = (const float*)d_in[5];
    const float* b1    = (const float*)d_in[6];
    const float* w2    = (const float*)d_in[7];
    const float* b2    = (const float*)d_in[8];
    float* out = (float*)d_out;

    cudaFuncSetAttribute(k1_tmp,   cudaFuncAttributeMaxDynamicSharedMemorySize, K1_SMEM);
    cudaFuncSetAttribute(k2_fused, cudaFuncAttributeMaxDynamicSharedMemorySize, K2_SMEM);

    k0_transpose<<<128, 256>>>(W_bil);
    k0x_convert<<<(BB * 512 * 64 + 255) / 256, 256>>>(x);
    k0w_fold<<<1, 128>>>(W1, ln_g, ln_b, b1);
    dim3 g1(128, (NBI + 127) / 128);   // 128 x 7
    k1_tmp<<<g1, 256, K1_SMEM>>>();
    k2_fused<<<NBI, 256, K2_SMEM>>>(b_bil, w2, b2);

    dim3 g3((LL + 31) / 32, (LL + 31) / 32, BB);   // 13 x 13 x 2
    k3_sym<<<g3, 256>>>(out);
}

// round 13
// speedup vs baseline: 1.0994x; 1.0994x over previous
#include <cuda_runtime.h>
#include <cuda_fp16.h>
#include <math.h>
#include <stdint.h>

#define BB 2
#define LL 401
#define DD 128
#define NBI (BB*LL)   // 802
#define HP 68         // smem row pitch in half2 (136 halfs, 272 B)

__device__ __half g_tmp_h[(size_t)NBI * DD * DD];             // 26.3 MB tmp[b,i,k,e] fp16
__device__ __align__(16) __half2 g_WbT[(size_t)DD * DD * 64]; // 4 MB: [k][e][d-pairs]
__device__ __align__(16) __half  g_x_h[(size_t)BB * 512 * DD];// padded fp16 x: [b][512][128]
__device__ __align__(16) __half  g_W1p[(size_t)DD * DD];      // W1[e][d]*ln_g[d] fp16
__device__ float  g_b1p[DD];                                  // b1 + ln_b @ W1^T
__device__ float  g_C[(size_t)BB * LL * LL];

// ---------------------------------------------------------------------------
__device__ __forceinline__ void mma_f16(float c[4],
                                        uint32_t a0, uint32_t a1, uint32_t a2, uint32_t a3,
                                        uint32_t b0, uint32_t b1)
{
    asm volatile(
        "mma.sync.aligned.m16n8k16.row.col.f32.f16.f16.f32 "
        "{%0,%1,%2,%3}, {%4,%5,%6,%7}, {%8,%9}, {%0,%1,%2,%3};"
        : "+f"(c[0]), "+f"(c[1]), "+f"(c[2]), "+f"(c[3])
        : "r"(a0), "r"(a1), "r"(a2), "r"(a3), "r"(b0), "r"(b1));
}
__device__ __forceinline__ void ldsm4(uint32_t r[4], uint32_t addr)
{
    asm volatile("ldmatrix.sync.aligned.m8n8.x4.shared.b16 {%0,%1,%2,%3}, [%4];"
                 : "=r"(r[0]), "=r"(r[1]), "=r"(r[2]), "=r"(r[3]) : "r"(addr));
}
__device__ __forceinline__ void barp(int id)
{
    asm volatile("bar.sync %0, 64;" :: "r"(id) : "memory");
}

// Branch-free GELU without the 0.5 (folded into w2): v*(1+erf(v/sqrt2)).
// A&S 7.1.26 erf, rcp.approx + expf (round-10 proven-best variant).
__device__ __forceinline__ float gelu2x(float v)
{
    float z   = v * 0.70710678118654752f;
    float az  = fabsf(z);
    float den = fmaf(0.3275911f, az, 1.0f);
    float t;
    asm("rcp.approx.f32 %0, %1;" : "=f"(t) : "f"(den));
    float e = __expf(-z * z);
    float p = fmaf(1.061405429f, t, -1.453152027f);
    p = fmaf(p, t, 1.421413741f);
    p = fmaf(p, t, -0.284496736f);
    p = fmaf(p, t, 0.254829592f);
    p = p * t;
    float erfa = fmaf(-p, e, 1.0f);
    float erfv = copysignf(erfa, z);
    return v * (1.0f + erfv);
}

// ---------------------------------------------------------------------------
// Kernel 0: one-time transpose W_bil[k][d][e] (fp32) -> g_WbT[k][e][d-pairs] (fp16)
// ---------------------------------------------------------------------------
__global__ __launch_bounds__(256, 2) void k0_transpose(const float* __restrict__ Wb)
{
    __shared__ __half Sg[128 * 130];
    const int k   = blockIdx.x;
    const int tid = threadIdx.x;
    const float* Wk = Wb + (size_t)k * DD * DD;

    #pragma unroll
    for (int s = 0; s < 16; ++s) {
        int v = tid + (s << 8);
        int d = v >> 5, e4 = (v & 31) << 2;
        float4 w = *(const float4*)&Wk[d * DD + e4];
        __half2* dst = (__half2*)&Sg[d * 130 + e4];
        dst[0] = __floats2half2_rn(w.x, w.y);
        dst[1] = __floats2half2_rn(w.z, w.w);
    }
    __syncthreads();

    __half2* out = g_WbT + (size_t)k * (DD * 64);
    #pragma unroll
    for (int s = 0; s < 32; ++s) {
        int v = tid + (s << 8);
        int e = v >> 6, d2 = v & 63;
        __half lo = Sg[(2 * d2) * 130 + e];
        __half hi = Sg[(2 * d2 + 1) * 130 + e];
        out[e * 64 + d2] = __halves2half2(lo, hi);
    }
}

// ---------------------------------------------------------------------------
// Kernel 0x: convert x (fp32) -> g_x_h fp16, padded to 512 rows per b.
// ---------------------------------------------------------------------------
__global__ __launch_bounds__(256) void k0x_convert(const float* __restrict__ x)
{
    int idx = blockIdx.x * 256 + threadIdx.x;
    if (idx >= BB * 512 * 64) return;
    int b   = idx >> 15;
    int rem = idx & 32767;
    int r   = rem >> 6, c2 = rem & 63;
    __half2 h;
    if (r < LL) {
        const float* sp = &x[((size_t)(b * LL + r)) * DD + c2 * 2];
        h = __floats2half2_rn(sp[0], sp[1]);
    } else {
        h = __floats2half2_rn(0.f, 0.f);
    }
    *(__half2*)&g_x_h[((size_t)(b * 512 + r)) * DD + c2 * 2] = h;
}

// ---------------------------------------------------------------------------
// Kernel 0w (PARALLEL): fold LN affine into W1. One block per e-row:
//   g_W1p[e][d] = fp16(W1[e][d] * ln_g[d]);  g_b1p[e] = b1[e] + sum_d ln_b[d]*W1[e][d]
// ---------------------------------------------------------------------------
__global__ __launch_bounds__(128) void k0w_fold(const float* __restrict__ W1,
                                                const float* __restrict__ ln_g,
                                                const float* __restrict__ ln_b,
                                                const float* __restrict__ b1)
{
    __shared__ float red[4];
    const int e = blockIdx.x, d = threadIdx.x;
    float w = W1[e * DD + d];
    g_W1p[e * DD + d] = __float2half_rn(w * ln_g[d]);
    float v = ln_b[d] * w;
    #pragma unroll
    for (int off = 16; off > 0; off >>= 1)
        v += __shfl_xor_sync(0xffffffffu, v, off);
    if ((d & 31) == 0) red[d >> 5] = v;
    __syncthreads();
    if (d == 0)
        g_b1p[e] = b1[e] + red[0] + red[1] + red[2] + red[3];
}

// ---------------------------------------------------------------------------
// Kernel 1 (fp16 mma + ldmatrix): tmp[bi][k][e] = sum_d x[bi][d]*W_bil[k][d][e]
// ---------------------------------------------------------------------------
#define K1_XS 0u
#define K1_WT 34816u
#define K1_SMEM 69632u

__global__ __launch_bounds__(256, 2) void k1_tmp()
{
    extern __shared__ char smc[];
    __half2* Xs = (__half2*)(smc + K1_XS);
    __half2* Wt = (__half2*)(smc + K1_WT);

    const int k   = blockIdx.x;
    const int bi0 = blockIdx.y * 128;
    const int tid = threadIdx.x, tx = tid & 31, wid = tid >> 5;
    const int wj  = wid & 3, wk = wid >> 2;
    const int g   = tx >> 2, c = tx & 3;
    const int arow = wj * 32, bcol = wk * 64;

    const __half2* Wsrc = g_WbT + (size_t)k * (DD * 64);
    #pragma unroll
    for (int s = 0; s < 8; ++s) {
        int v = tid + (s << 8);
        int row = v >> 4, u = (v & 15) << 2;
        uint4 t = *(const uint4*)&Wsrc[row * 64 + u];
        *(uint4*)&Wt[row * HP + u] = t;
    }
    #pragma unroll
    for (int s = 0; s < 8; ++s) {
        int v = tid + (s << 8);
        int row = v >> 4, seg = v & 15;
        int bi = bi0 + row;
        int bb_ = (bi >= LL) ? 1 : 0;
        int r = bi - bb_ * LL;
        uint4 t = *(const uint4*)&g_x_h[((size_t)(bb_ * 512 + r)) * DD + seg * 8];
        *(uint4*)((char*)Xs + row * 272 + seg * 16) = t;
    }
    __syncthreads();

    const uint32_t sb  = (uint32_t)__cvta_generic_to_shared(smc);
    const uint32_t sbX = sb + K1_XS, sbW = sb + K1_WT;

    uint32_t aAddr[2], bOff[4];
    #pragma unroll
    for (int mf = 0; mf < 2; ++mf) {
        int row = arow + mf * 16 + (tx & 7) + ((tx & 8) ? 8 : 0);
        aAddr[mf] = sbX + row * 272 + ((tx & 16) ? 16 : 0);
    }
    #pragma unroll
    for (int p = 0; p < 4; ++p) {
        int row = bcol + p * 16 + (tx & 7) + ((tx & 16) ? 8 : 0);
        bOff[p] = row * 272 + ((tx & 8) ? 16 : 0);
    }

    float acc[2][8][4];
    #pragma unroll
    for (int mf = 0; mf < 2; ++mf)
        #pragma unroll
        for (int nt = 0; nt < 8; ++nt)
            #pragma unroll
            for (int u = 0; u < 4; ++u) acc[mf][nt][u] = 0.0f;

    #pragma unroll
    for (int kc = 0; kc < 8; ++kc) {
        int ko = kc * 32;
        uint32_t a0[4], a1[4];
        ldsm4(a0, aAddr[0] + ko);
        ldsm4(a1, aAddr[1] + ko);
        #pragma unroll
        for (int p = 0; p < 4; ++p) {
            uint32_t bb[4];
            ldsm4(bb, sbW + bOff[p] + ko);
            mma_f16(acc[0][2 * p],     a0[0], a0[1], a0[2], a0[3], bb[0], bb[1]);
            mma_f16(acc[1][2 * p],     a1[0], a1[1], a1[2], a1[3], bb[0], bb[1]);
            mma_f16(acc[0][2 * p + 1], a0[0], a0[1], a0[2], a0[3], bb[2], bb[3]);
            mma_f16(acc[1][2 * p + 1], a1[0], a1[1], a1[2], a1[3], bb[2], bb[3]);
        }
    }

    #pragma unroll
    for (int mf = 0; mf < 2; ++mf)
        #pragma unroll
        for (int nt = 0; nt < 8; ++nt) {
            int r0  = bi0 + arow + mf * 16 + g;
            int col = bcol + nt * 8 + 2 * c;
            if (r0 < NBI)
                *(__half2*)&g_tmp_h[(size_t)r0 * (DD * DD) + k * DD + col] =
                    __floats2half2_rn(acc[mf][nt][0], acc[mf][nt][1]);
            int r1 = r0 + 8;
            if (r1 < NBI)
                *(__half2*)&g_tmp_h[(size_t)r1 * (DD * DD) + k * DD + col] =
                    __floats2half2_rn(acc[mf][nt][2], acc[mf][nt][3]);
        }
}

// ---------------------------------------------------------------------------
// Kernel 2 (round-10 structure): per (b,i) CTA, warp-pair independent,
// tiles {128,128,128,32}; LN affine pre-folded into g_W1p/g_b1p.
// ---------------------------------------------------------------------------
#define K2_TS 0u
#define K2_WS 34816u
#define K2_XS 69632u
#define K2_CV 104448u        // 384 floats: bbs, b1s, w2s
#define K2_RA 107008u
#define K2_RB 109056u
#define K2_SMEM 110080u

__global__ __launch_bounds__(256, 2) void k2_fused(
    const float* __restrict__ b_bil, const float* __restrict__ w2,
    const float* __restrict__ b2)
{
    extern __shared__ char smc[];
    __half2* Ts  = (__half2*)(smc + K2_TS);
    __half2* W1s = (__half2*)(smc + K2_WS);
    __half2* Xs  = (__half2*)(smc + K2_XS);
    float* cv  = (float*)(smc + K2_CV);
    float* bbs = cv; float* b1s = cv + 128; float* w2s = cv + 256;
    float2* redA = (float2*)(smc + K2_RA);
    float*  redB = (float*) (smc + K2_RB);

    const int bi  = blockIdx.x;
    const int b   = bi / LL;
    const int tid = threadIdx.x, tx = tid & 31, wid = tid >> 5;
    const int wj  = wid & 3, wk = wid >> 2;
    const int g   = tx >> 2, c = tx & 3;
    const int arow = wj * 32, bcol = wk * 64;
    const int pt  = wk * 32 + tx;          // thread index within pair [0,64)
    const int pb  = wj + 1;                // named barrier id

    // Ts: raw fp16 copy of tmp_i.  W1s: raw fp16 copy of pre-folded W1'.
    const __half* tp = g_tmp_h + (size_t)bi * DD * DD;
    #pragma unroll
    for (int s = 0; s < 8; ++s) {
        int v = tid + (s << 8);
        int row = v >> 4, seg = (v & 15) << 3;
        uint4 tv = *(const uint4*)&tp[row * DD + seg];
        *(uint4*)((char*)Ts + row * 272 + seg * 2) = tv;
        uint4 wv = *(const uint4*)&g_W1p[row * DD + seg];
        *(uint4*)((char*)W1s + row * 272 + seg * 2) = wv;
    }
    if (tid < 128) {
        bbs[tid] = b_bil[tid];
        b1s[tid] = g_b1p[tid];
        w2s[tid] = 0.5f * w2[tid];   // GELU 0.5 folded
    }
    const float b2v = b2[0];
    const __half* xh = g_x_h + (size_t)b * 512 * DD;
    float* Crow = g_C + (size_t)bi * LL;

    const uint32_t sb  = (uint32_t)__cvta_generic_to_shared(smc);
    const uint32_t sbX = sb + K2_XS, sbT = sb + K2_TS, sbW = sb + K2_WS;

    uint32_t aAddr[2], bOff[4];
    #pragma unroll
    for (int mf = 0; mf < 2; ++mf) {
        int row = arow + mf * 16 + (tx & 7) + ((tx & 8) ? 8 : 0);
        aAddr[mf] = sbX + row * 272 + ((tx & 16) ? 16 : 0);
    }
    #pragma unroll
    for (int p = 0; p < 4; ++p) {
        int row = bcol + p * 16 + (tx & 7) + ((tx & 16) ? 8 : 0);
        bOff[p] = row * 272 + ((tx & 8) ? 16 : 0);
    }
    __syncthreads();   // Ts/W1s/constants visible; last CTA-wide sync

    #pragma unroll 1
    for (int t = 0; t < 4; ++t) {
        const int j0 = t * 128;
        const int mrows = (t == 3) ? 32 : 128;
        if (arow >= mrows) continue;   // whole pair skips tail together

        // ---- Pair loads its own 32 X rows (raw fp16 copy) ----
        #pragma unroll
        for (int s = 0; s < 8; ++s) {
            int u = pt + (s << 6);
            int row = arow + (u >> 4), seg = u & 15;
            uint4 tv = *(const uint4*)&xh[((size_t)(j0 + row)) * DD + seg * 8];
            *(uint4*)((char*)Xs + row * 272 + seg * 16) = tv;
        }
        barp(pb);

        // ---- Phase A: pair = X @ Ts^T ----
        float acc[2][8][4];
        #pragma unroll
        for (int mf = 0; mf < 2; ++mf)
            #pragma unroll
            for (int nt = 0; nt < 8; ++nt)
                #pragma unroll
                for (int u = 0; u < 4; ++u) acc[mf][nt][u] = 0.0f;

        #pragma unroll
        for (int kc = 0; kc < 8; ++kc) {
            int ko = kc * 32;
            uint32_t a0[4], a1[4];
            ldsm4(a0, aAddr[0] + ko);
            ldsm4(a1, aAddr[1] + ko);
            #pragma unroll
            for (int p = 0; p < 4; ++p) {
                uint32_t bb[4];
                ldsm4(bb, sbT + bOff[p] + ko);
                mma_f16(acc[0][2 * p],     a0[0], a0[1], a0[2], a0[3], bb[0], bb[1]);
                mma_f16(acc[1][2 * p],     a1[0], a1[1], a1[2], a1[3], bb[0], bb[1]);
                mma_f16(acc[0][2 * p + 1], a0[0], a0[1], a0[2], a0[3], bb[2], bb[3]);
                mma_f16(acc[1][2 * p + 1], a1[0], a1[1], a1[2], a1[3], bb[2], bb[3]);
            }
        }

        // ---- LN stats ----
        float s1[4] = {0.f, 0.f, 0.f, 0.f}, s2[4] = {0.f, 0.f, 0.f, 0.f};
        #pragma unroll
        for (int mf = 0; mf < 2; ++mf)
            #pragma unroll
            for (int nt = 0; nt < 8; ++nt) {
                int col = bcol + nt * 8 + 2 * c;
                float bb0 = bbs[col], bb1 = bbs[col + 1];
                acc[mf][nt][0] += bb0; acc[mf][nt][1] += bb1;
                acc[mf][nt][2] += bb0; acc[mf][nt][3] += bb1;
                s1[mf * 2]     += acc[mf][nt][0] + acc[mf][nt][1];
                s2[mf * 2]     += acc[mf][nt][0] * acc[mf][nt][0] + acc[mf][nt][1] * acc[mf][nt][1];
                s1[mf * 2 + 1] += acc[mf][nt][2] + acc[mf][nt][3];
                s2[mf * 2 + 1] += acc[mf][nt][2] * acc[mf][nt][2] + acc[mf][nt][3] * acc[mf][nt][3];
            }
        #pragma unroll
        for (int off = 1; off <= 2; off <<= 1)
            #pragma unroll
            for (int lr = 0; lr < 4; ++lr) {
                s1[lr] += __shfl_xor_sync(0xffffffffu, s1[lr], off);
                s2[lr] += __shfl_xor_sync(0xffffffffu, s2[lr], off);
            }
        if (c == 0) {
            #pragma unroll
            for (int lr = 0; lr < 4; ++lr) {
                int row = arow + (lr >> 1) * 16 + (lr & 1) * 8 + g;
                redA[row * 2 + wk] = make_float2(s1[lr], s2[lr]);
            }
        }
        barp(pb);

        float mu[4], rs[4];
        #pragma unroll
        for (int lr = 0; lr < 4; ++lr) {
            int row = arow + (lr >> 1) * 16 + (lr & 1) * 8 + g;
            float2 rA = redA[row * 2 + 0], rB = redA[row * 2 + 1];
            float S1 = rA.x + rB.x, S2 = rA.y + rB.y;
            mu[lr] = S1 * (1.0f / 128.0f);
            rs[lr] = rsqrtf(S2 * (1.0f / 128.0f) - mu[lr] * mu[lr] + 1e-5f);
        }
        // ---- Write H = (pair - mu)*rs (fp16) into Xs; LN affine is in W1' ----
        #pragma unroll
        for (int mf = 0; mf < 2; ++mf)
            #pragma unroll
            for (int nt = 0; nt < 8; ++nt) {
                int col = bcol + nt * 8 + 2 * c;
                int h2i = (col >> 1);
                int lr0 = mf * 2, lr1 = mf * 2 + 1;
                int r0 = arow + mf * 16 + g;
                Xs[r0 * HP + h2i] = __floats2half2_rn(
                    (acc[mf][nt][0] - mu[lr0]) * rs[lr0],
                    (acc[mf][nt][1] - mu[lr0]) * rs[lr0]);
                Xs[(r0 + 8) * HP + h2i] = __floats2half2_rn(
                    (acc[mf][nt][2] - mu[lr1]) * rs[lr1],
                    (acc[mf][nt][3] - mu[lr1]) * rs[lr1]);
            }
        barp(pb);

        // ---- Phase B: o = H @ W1'^T ----
        #pragma unroll
        for (int mf = 0; mf < 2; ++mf)
            #pragma unroll
            for (int nt = 0; nt < 8; ++nt)
                #pragma unroll
                for (int u = 0; u < 4; ++u) acc[mf][nt][u] = 0.0f;

        #pragma unroll
        for (int kc = 0; kc < 8; ++kc) {
            int ko = kc * 32;
            uint32_t a0[4], a1[4];
            ldsm4(a0, aAddr[0] + ko);
            ldsm4(a1, aAddr[1] + ko);
            #pragma unroll
            for (int p = 0; p < 4; ++p) {
                uint32_t bb[4];
                ldsm4(bb, sbW + bOff[p] + ko);
                mma_f16(acc[0][2 * p],     a0[0], a0[1], a0[2], a0[3], bb[0], bb[1]);
                mma_f16(acc[1][2 * p],     a1[0], a1[1], a1[2], a1[3], bb[0], bb[1]);
                mma_f16(acc[0][2 * p + 1], a0[0], a0[1], a0[2], a0[3], bb[2], bb[3]);
                mma_f16(acc[1][2 * p + 1], a1[0], a1[1], a1[2], a1[3], bb[2], bb[3]);
            }
        }

        // ---- Epilogue: bias (pre-folded), GELU, dot w2 ----
        float tsum[4] = {0.f, 0.f, 0.f, 0.f};
        #pragma unroll
        for (int mf = 0; mf < 2; ++mf)
            #pragma unroll
            for (int nt = 0; nt < 8; ++nt) {
                int col = bcol + nt * 8 + 2 * c;
                float c0 = b1s[col], c1 = b1s[col + 1];
                float w0 = w2s[col], w1 = w2s[col + 1];
                tsum[mf * 2]     += gelu2x(acc[mf][nt][0] + c0) * w0
                                  + gelu2x(acc[mf][nt][1] + c1) * w1;
                tsum[mf * 2 + 1] += gelu2x(acc[mf][nt][2] + c0) * w0
                                  + gelu2x(acc[mf][nt][3] + c1) * w1;
            }
        #pragma unroll
        for (int off = 1; off <= 2; off <<= 1)
            #pragma unroll
            for (int lr = 0; lr < 4; ++lr)
                tsum[lr] += __shfl_xor_sync(0xffffffffu, tsum[lr], off);
        if (c == 0) {
            #pragma unroll
            for (int lr = 0; lr < 4; ++lr) {
                int row = arow + (lr >> 1) * 16 + (lr & 1) * 8 + g;
                redB[row * 2 + wk] = tsum[lr];
            }
        }
        barp(pb);

        // ---- C write ----
        if (wk == 0) {
            int row = arow + tx;
            int j = j0 + row;
            if (row < mrows && j < LL)
                Crow[j] = redB[row * 2] + redB[row * 2 + 1] + b2v;
        }
    }
}

// ---------------------------------------------------------------------------
// Kernel 3: out[b,i,j] = 0.5*(C[b,i,j] + C[b,j,i]) with smem tile transpose.
// ---------------------------------------------------------------------------
__global__ __launch_bounds__(256) void k3_sym(float* __restrict__ out)
{
    __shared__ float tA[32][33];
    __shared__ float tB[32][33];
    const int b  = blockIdx.z;
    const int i0 = blockIdx.y * 32, j0 = blockIdx.x * 32;
    const int tx = threadIdx.x & 31, ty = threadIdx.x >> 5;
    const float* Cb = g_C + (size_t)b * LL * LL;

    #pragma unroll
    for (int r = 0; r < 4; ++r) {
        int row = ty + r * 8;
        int gi = i0 + row, gj = j0 + tx;
        tA[row][tx] = (gi < LL && gj < LL) ? Cb[gi * LL + gj] : 0.f;
        int hi = j0 + row, hj = i0 + tx;
        tB[row][tx] = (hi < LL && hj < LL) ? Cb[hi * LL + hj] : 0.f;
    }
    __syncthreads();

    float* Ob = out + (size_t)b * LL * LL;
    #pragma unroll
    for (int r = 0; r < 4; ++r) {
        int row = ty + r * 8;
        int gi = i0 + row, gj = j0 + tx;
        if (gi < LL && gj < LL)
            Ob[gi * LL + gj] = 0.5f * (tA[row][tx] + tB[tx][row]);
    }
}

// ---------------------------------------------------------------------------
extern "C" void kernel_launch(void* const* d_in, const int* in_sizes, int n_in,
                              void* d_out, int out_size)
{
    (void)in_sizes; (void)n_in; (void)out_size;
    const float* x     = (const float*)d_in[0];
    const float* W_bil = (const float*)d_in[1];
    const float* b_bil = (const float*)d_in[2];
    const float* ln_g  = (const float*)d_in[3];
    const float* ln_b  = (const float*)d_in[4];
    const float* W1    = (const float*)d_in[5];
    const float* b1    = (const float*)d_in[6];
    const float* w2    = (const float*)d_in[7];
    const float* b2    = (const float*)d_in[8];
    float* out = (float*)d_out;

    cudaFuncSetAttribute(k1_tmp,   cudaFuncAttributeMaxDynamicSharedMemorySize, K1_SMEM);
    cudaFuncSetAttribute(k2_fused, cudaFuncAttributeMaxDynamicSharedMemorySize, K2_SMEM);

    k0_transpose<<<128, 256>>>(W_bil);
    k0x_convert<<<(BB * 512 * 64 + 255) / 256, 256>>>(x);
    k0w_fold<<<128, 128>>>(W1, ln_g, ln_b, b1);
    dim3 g1(128, (NBI + 127) / 128);   // 128 x 7
    k1_tmp<<<g1, 256, K1_SMEM>>>();
    k2_fused<<<NBI, 256, K2_SMEM>>>(b_bil, w2, b2);

    dim3 g3((LL + 31) / 32, (LL + 31) / 32, BB);   // 13 x 13 x 2
    k3_sym<<<g3, 256>>>(out);
}

// round 14
// speedup vs baseline: 1.1316x; 1.0293x over previous
#include <cuda_runtime.h>
#include <cuda_fp16.h>
#include <math.h>
#include <stdint.h>

#define BB 2
#define LL 401
#define DD 128
#define NBI (BB*LL)   // 802
#define HP 68         // smem row pitch in half2 (136 halfs, 272 B)

__device__ __half g_tmp_h[(size_t)NBI * DD * DD];             // 26.3 MB tmp[b,i,k,e] fp16
__device__ __align__(16) __half2 g_WbT[(size_t)DD * DD * 64]; // 4 MB: [k][e][d-pairs]
__device__ __align__(16) __half  g_x_h[(size_t)BB * 512 * DD];// padded fp16 x: [b][512][128]
__device__ __align__(16) __half  g_W1p[(size_t)DD * DD];      // W1[e][d]*ln_g[d] fp16
__device__ float  g_b1p[DD];                                  // b1 + ln_b @ W1^T
__device__ float  g_C[(size_t)BB * LL * LL];

// ---------------------------------------------------------------------------
__device__ __forceinline__ void mma_f16(float c[4],
                                        uint32_t a0, uint32_t a1, uint32_t a2, uint32_t a3,
                                        uint32_t b0, uint32_t b1)
{
    asm volatile(
        "mma.sync.aligned.m16n8k16.row.col.f32.f16.f16.f32 "
        "{%0,%1,%2,%3}, {%4,%5,%6,%7}, {%8,%9}, {%0,%1,%2,%3};"
        : "+f"(c[0]), "+f"(c[1]), "+f"(c[2]), "+f"(c[3])
        : "r"(a0), "r"(a1), "r"(a2), "r"(a3), "r"(b0), "r"(b1));
}
__device__ __forceinline__ void ldsm4(uint32_t r[4], uint32_t addr)
{
    asm volatile("ldmatrix.sync.aligned.m8n8.x4.shared.b16 {%0,%1,%2,%3}, [%4];"
                 : "=r"(r[0]), "=r"(r[1]), "=r"(r[2]), "=r"(r[3]) : "r"(addr));
}

// Branch-free GELU without the 0.5 (folded into w2): v*(1+erf(v/sqrt2)).
__device__ __forceinline__ float gelu2x(float v)
{
    float z   = v * 0.70710678118654752f;
    float az  = fabsf(z);
    float den = fmaf(0.3275911f, az, 1.0f);
    float t;
    asm("rcp.approx.f32 %0, %1;" : "=f"(t) : "f"(den));
    float e = __expf(-z * z);
    float p = fmaf(1.061405429f, t, -1.453152027f);
    p = fmaf(p, t, 1.421413741f);
    p = fmaf(p, t, -0.284496736f);
    p = fmaf(p, t, 0.254829592f);
    p = p * t;
    float erfa = fmaf(-p, e, 1.0f);
    float erfv = copysignf(erfa, z);
    return v * (1.0f + erfv);
}

// ---------------------------------------------------------------------------
// Kernel 0: one-time transpose W_bil[k][d][e] (fp32) -> g_WbT[k][e][d-pairs] (fp16)
// ---------------------------------------------------------------------------
__global__ __launch_bounds__(256, 2) void k0_transpose(const float* __restrict__ Wb)
{
    __shared__ __half Sg[128 * 130];
    const int k   = blockIdx.x;
    const int tid = threadIdx.x;
    const float* Wk = Wb + (size_t)k * DD * DD;

    #pragma unroll
    for (int s = 0; s < 16; ++s) {
        int v = tid + (s << 8);
        int d = v >> 5, e4 = (v & 31) << 2;
        float4 w = *(const float4*)&Wk[d * DD + e4];
        __half2* dst = (__half2*)&Sg[d * 130 + e4];
        dst[0] = __floats2half2_rn(w.x, w.y);
        dst[1] = __floats2half2_rn(w.z, w.w);
    }
    __syncthreads();

    __half2* out = g_WbT + (size_t)k * (DD * 64);
    #pragma unroll
    for (int s = 0; s < 32; ++s) {
        int v = tid + (s << 8);
        int e = v >> 6, d2 = v & 63;
        __half lo = Sg[(2 * d2) * 130 + e];
        __half hi = Sg[(2 * d2 + 1) * 130 + e];
        out[e * 64 + d2] = __halves2half2(lo, hi);
    }
}

// ---------------------------------------------------------------------------
// Kernel 0x: convert x (fp32) -> g_x_h fp16, padded to 512 rows per b.
// ---------------------------------------------------------------------------
__global__ __launch_bounds__(256) void k0x_convert(const float* __restrict__ x)
{
    int idx = blockIdx.x * 256 + threadIdx.x;
    if (idx >= BB * 512 * 64) return;
    int b   = idx >> 15;
    int rem = idx & 32767;
    int r   = rem >> 6, c2 = rem & 63;
    __half2 h;
    if (r < LL) {
        const float* sp = &x[((size_t)(b * LL + r)) * DD + c2 * 2];
        h = __floats2half2_rn(sp[0], sp[1]);
    } else {
        h = __floats2half2_rn(0.f, 0.f);
    }
    *(__half2*)&g_x_h[((size_t)(b * 512 + r)) * DD + c2 * 2] = h;
}

// ---------------------------------------------------------------------------
// Kernel 0w (parallel): fold LN affine into W1.
// ---------------------------------------------------------------------------
__global__ __launch_bounds__(128) void k0w_fold(const float* __restrict__ W1,
                                                const float* __restrict__ ln_g,
                                                const float* __restrict__ ln_b,
                                                const float* __restrict__ b1)
{
    __shared__ float red[4];
    const int e = blockIdx.x, d = threadIdx.x;
    float w = W1[e * DD + d];
    g_W1p[e * DD + d] = __float2half_rn(w * ln_g[d]);
    float v = ln_b[d] * w;
    #pragma unroll
    for (int off = 16; off > 0; off >>= 1)
        v += __shfl_xor_sync(0xffffffffu, v, off);
    if ((d & 31) == 0) red[d >> 5] = v;
    __syncthreads();
    if (d == 0)
        g_b1p[e] = b1[e] + red[0] + red[1] + red[2] + red[3];
}

// ---------------------------------------------------------------------------
// Kernel 1 (fp16 mma + ldmatrix): tmp[bi][k][e] = sum_d x[bi][d]*W_bil[k][d][e]
// ---------------------------------------------------------------------------
#define K1_XS 0u
#define K1_WT 34816u
#define K1_SMEM 69632u

__global__ __launch_bounds__(256, 2) void k1_tmp()
{
    extern __shared__ char smc[];
    __half2* Xs = (__half2*)(smc + K1_XS);
    __half2* Wt = (__half2*)(smc + K1_WT);

    const int k   = blockIdx.x;
    const int bi0 = blockIdx.y * 128;
    const int tid = threadIdx.x, tx = tid & 31, wid = tid >> 5;
    const int wj  = wid & 3, wk = wid >> 2;
    const int g   = tx >> 2, c = tx & 3;
    const int arow = wj * 32, bcol = wk * 64;

    const __half2* Wsrc = g_WbT + (size_t)k * (DD * 64);
    #pragma unroll
    for (int s = 0; s < 8; ++s) {
        int v = tid + (s << 8);
        int row = v >> 4, u = (v & 15) << 2;
        uint4 t = *(const uint4*)&Wsrc[row * 64 + u];
        *(uint4*)&Wt[row * HP + u] = t;
    }
    #pragma unroll
    for (int s = 0; s < 8; ++s) {
        int v = tid + (s << 8);
        int row = v >> 4, seg = v & 15;
        int bi = bi0 + row;
        int bb_ = (bi >= LL) ? 1 : 0;
        int r = bi - bb_ * LL;
        uint4 t = *(const uint4*)&g_x_h[((size_t)(bb_ * 512 + r)) * DD + seg * 8];
        *(uint4*)((char*)Xs + row * 272 + seg * 16) = t;
    }
    __syncthreads();

    const uint32_t sb  = (uint32_t)__cvta_generic_to_shared(smc);
    const uint32_t sbX = sb + K1_XS, sbW = sb + K1_WT;

    uint32_t aAddr[2], bOff[4];
    #pragma unroll
    for (int mf = 0; mf < 2; ++mf) {
        int row = arow + mf * 16 + (tx & 7) + ((tx & 8) ? 8 : 0);
        aAddr[mf] = sbX + row * 272 + ((tx & 16) ? 16 : 0);
    }
    #pragma unroll
    for (int p = 0; p < 4; ++p) {
        int row = bcol + p * 16 + (tx & 7) + ((tx & 16) ? 8 : 0);
        bOff[p] = row * 272 + ((tx & 8) ? 16 : 0);
    }

    float acc[2][8][4];
    #pragma unroll
    for (int mf = 0; mf < 2; ++mf)
        #pragma unroll
        for (int nt = 0; nt < 8; ++nt)
            #pragma unroll
            for (int u = 0; u < 4; ++u) acc[mf][nt][u] = 0.0f;

    #pragma unroll
    for (int kc = 0; kc < 8; ++kc) {
        int ko = kc * 32;
        uint32_t a0[4], a1[4];
        ldsm4(a0, aAddr[0] + ko);
        ldsm4(a1, aAddr[1] + ko);
        #pragma unroll
        for (int p = 0; p < 4; ++p) {
            uint32_t bb[4];
            ldsm4(bb, sbW + bOff[p] + ko);
            mma_f16(acc[0][2 * p],     a0[0], a0[1], a0[2], a0[3], bb[0], bb[1]);
            mma_f16(acc[1][2 * p],     a1[0], a1[1], a1[2], a1[3], bb[0], bb[1]);
            mma_f16(acc[0][2 * p + 1], a0[0], a0[1], a0[2], a0[3], bb[2], bb[3]);
            mma_f16(acc[1][2 * p + 1], a1[0], a1[1], a1[2], a1[3], bb[2], bb[3]);
        }
    }

    #pragma unroll
    for (int mf = 0; mf < 2; ++mf)
        #pragma unroll
        for (int nt = 0; nt < 8; ++nt) {
            int r0  = bi0 + arow + mf * 16 + g;
            int col = bcol + nt * 8 + 2 * c;
            if (r0 < NBI)
                *(__half2*)&g_tmp_h[(size_t)r0 * (DD * DD) + k * DD + col] =
                    __floats2half2_rn(acc[mf][nt][0], acc[mf][nt][1]);
            int r1 = r0 + 8;
            if (r1 < NBI)
                *(__half2*)&g_tmp_h[(size_t)r1 * (DD * DD) + k * DD + col] =
                    __floats2half2_rn(acc[mf][nt][2], acc[mf][nt][3]);
        }
}

// ---------------------------------------------------------------------------
// Kernel 2 (fully warp-synchronous): per (b,i) CTA. Each warp owns 16 j-rows
// x 128 cols end-to-end; NO named barriers, NO smem reductions. Only the
// initial __syncthreads (Ts/W1s/consts) and __syncwarp around H.
// ---------------------------------------------------------------------------
#define K2_TS 0u
#define K2_WS 34816u
#define K2_XS 69632u
#define K2_CV 104448u        // 384 floats: bbs, b1s, w2s
#define K2_SMEM 106240u

__global__ __launch_bounds__(256, 2) void k2_fused(
    const float* __restrict__ b_bil, const float* __restrict__ w2,
    const float* __restrict__ b2)
{
    extern __shared__ char smc[];
    __half2* Ts  = (__half2*)(smc + K2_TS);
    __half2* W1s = (__half2*)(smc + K2_WS);
    __half2* Xs  = (__half2*)(smc + K2_XS);
    float* cv  = (float*)(smc + K2_CV);
    float* bbs = cv; float* b1s = cv + 128; float* w2s = cv + 256;

    const int bi  = blockIdx.x;
    const int b   = bi / LL;
    const int tid = threadIdx.x, tx = tid & 31, wid = tid >> 5;
    const int g   = tx >> 2, c = tx & 3;
    const int arow = wid * 16;

    // Ts: raw fp16 copy of tmp_i.  W1s: raw fp16 copy of pre-folded W1'.
    const __half* tp = g_tmp_h + (size_t)bi * DD * DD;
    #pragma unroll
    for (int s = 0; s < 8; ++s) {
        int v = tid + (s << 8);
        int row = v >> 4, seg = (v & 15) << 3;
        uint4 tv = *(const uint4*)&tp[row * DD + seg];
        *(uint4*)((char*)Ts + row * 272 + seg * 2) = tv;
        uint4 wv = *(const uint4*)&g_W1p[row * DD + seg];
        *(uint4*)((char*)W1s + row * 272 + seg * 2) = wv;
    }
    if (tid < 128) {
        bbs[tid] = b_bil[tid];
        b1s[tid] = g_b1p[tid];
        w2s[tid] = 0.5f * w2[tid];   // GELU 0.5 folded
    }
    const float b2v = b2[0];
    const __half* xh = g_x_h + (size_t)b * 512 * DD;
    float* Crow = g_C + (size_t)bi * LL;

    const uint32_t sb  = (uint32_t)__cvta_generic_to_shared(smc);
    const uint32_t sbX = sb + K2_XS, sbT = sb + K2_TS, sbW = sb + K2_WS;

    const uint32_t aAddr =
        sbX + (arow + (tx & 7) + ((tx & 8) ? 8 : 0)) * 272 + ((tx & 16) ? 16 : 0);
    uint32_t bOff[8];
    #pragma unroll
    for (int p = 0; p < 8; ++p) {
        int row = p * 16 + (tx & 7) + ((tx & 16) ? 8 : 0);
        bOff[p] = row * 272 + ((tx & 8) ? 16 : 0);
    }
    __syncthreads();   // Ts/W1s/constants visible; the ONLY CTA-wide sync

    #pragma unroll 1
    for (int t = 0; t < 4; ++t) {
        const int j0 = t * 128;
        const int mrows = (t == 3) ? 32 : 128;
        if (arow >= mrows) continue;   // whole warp skips together

        // ---- Warp loads its own 16 X rows (raw fp16, 8 uint4/thread) ----
        #pragma unroll
        for (int s = 0; s < 8; ++s) {
            int u = tx + (s << 5);          // 256 uint4 per warp
            int row = arow + (u >> 4), seg = u & 15;
            uint4 tv = *(const uint4*)&xh[((size_t)(j0 + row)) * DD + seg * 8];
            *(uint4*)((char*)Xs + row * 272 + seg * 16) = tv;
        }
        __syncwarp();

        // ---- Phase A: pair = X @ Ts^T (warp tile 16m x 128n) ----
        float acc[16][4];
        #pragma unroll
        for (int nt = 0; nt < 16; ++nt)
            #pragma unroll
            for (int u = 0; u < 4; ++u) acc[nt][u] = 0.0f;

        #pragma unroll
        for (int kc = 0; kc < 8; ++kc) {
            int ko = kc * 32;
            uint32_t a0[4];
            ldsm4(a0, aAddr + ko);
            #pragma unroll
            for (int p = 0; p < 8; ++p) {
                uint32_t bb[4];
                ldsm4(bb, sbT + bOff[p] + ko);
                mma_f16(acc[2 * p],     a0[0], a0[1], a0[2], a0[3], bb[0], bb[1]);
                mma_f16(acc[2 * p + 1], a0[0], a0[1], a0[2], a0[3], bb[2], bb[3]);
            }
        }

        // ---- LN stats: thread holds ALL 128 cols of its 2 rows ----
        float s1a = 0.f, s2a = 0.f, s1b = 0.f, s2b = 0.f;
        #pragma unroll
        for (int nt = 0; nt < 16; ++nt) {
            int col = nt * 8 + 2 * c;
            float bb0 = bbs[col], bb1 = bbs[col + 1];
            acc[nt][0] += bb0; acc[nt][1] += bb1;
            acc[nt][2] += bb0; acc[nt][3] += bb1;
            s1a += acc[nt][0] + acc[nt][1];
            s2a += acc[nt][0] * acc[nt][0] + acc[nt][1] * acc[nt][1];
            s1b += acc[nt][2] + acc[nt][3];
            s2b += acc[nt][2] * acc[nt][2] + acc[nt][3] * acc[nt][3];
        }
        #pragma unroll
        for (int off = 1; off <= 2; off <<= 1) {
            s1a += __shfl_xor_sync(0xffffffffu, s1a, off);
            s2a += __shfl_xor_sync(0xffffffffu, s2a, off);
            s1b += __shfl_xor_sync(0xffffffffu, s1b, off);
            s2b += __shfl_xor_sync(0xffffffffu, s2b, off);
        }
        float mua = s1a * (1.0f / 128.0f);
        float rsa = rsqrtf(s2a * (1.0f / 128.0f) - mua * mua + 1e-5f);
        float mub = s1b * (1.0f / 128.0f);
        float rsb = rsqrtf(s2b * (1.0f / 128.0f) - mub * mub + 1e-5f);

        // ---- Write H = (pair - mu)*rs (fp16) into own Xs rows ----
        #pragma unroll
        for (int nt = 0; nt < 16; ++nt) {
            int col = nt * 8 + 2 * c;
            int h2i = (col >> 1);
            Xs[(arow + g) * HP + h2i] = __floats2half2_rn(
                (acc[nt][0] - mua) * rsa, (acc[nt][1] - mua) * rsa);
            Xs[(arow + 8 + g) * HP + h2i] = __floats2half2_rn(
                (acc[nt][2] - mub) * rsb, (acc[nt][3] - mub) * rsb);
        }
        __syncwarp();

        // ---- Phase B: o = H @ W1'^T ----
        #pragma unroll
        for (int nt = 0; nt < 16; ++nt)
            #pragma unroll
            for (int u = 0; u < 4; ++u) acc[nt][u] = 0.0f;

        #pragma unroll
        for (int kc = 0; kc < 8; ++kc) {
            int ko = kc * 32;
            uint32_t a0[4];
            ldsm4(a0, aAddr + ko);
            #pragma unroll
            for (int p = 0; p < 8; ++p) {
                uint32_t bb[4];
                ldsm4(bb, sbW + bOff[p] + ko);
                mma_f16(acc[2 * p],     a0[0], a0[1], a0[2], a0[3], bb[0], bb[1]);
                mma_f16(acc[2 * p + 1], a0[0], a0[1], a0[2], a0[3], bb[2], bb[3]);
            }
        }

        // ---- Epilogue: bias, GELU, full-row dot -> direct C write ----
        float ta = 0.f, tb = 0.f;
        #pragma unroll
        for (int nt = 0; nt < 16; ++nt) {
            int col = nt * 8 + 2 * c;
            float c0 = b1s[col], c1 = b1s[col + 1];
            float w0 = w2s[col], w1 = w2s[col + 1];
            ta += gelu2x(acc[nt][0] + c0) * w0 + gelu2x(acc[nt][1] + c1) * w1;
            tb += gelu2x(acc[nt][2] + c0) * w0 + gelu2x(acc[nt][3] + c1) * w1;
        }
        #pragma unroll
        for (int off = 1; off <= 2; off <<= 1) {
            ta += __shfl_xor_sync(0xffffffffu, ta, off);
            tb += __shfl_xor_sync(0xffffffffu, tb, off);
        }
        if (c == 0) {
            int ja = j0 + arow + g;
            int jb = ja + 8;
            if (ja < LL) Crow[ja] = ta + b2v;
            if (jb < LL) Crow[jb] = tb + b2v;
        }
        // no barrier: next-tile Xs writes are by this warp only (__syncwarp covers)
    }
}

// ---------------------------------------------------------------------------
// Kernel 3: out[b,i,j] = 0.5*(C[b,i,j] + C[b,j,i]) with smem tile transpose.
// ---------------------------------------------------------------------------
__global__ __launch_bounds__(256) void k3_sym(float* __restrict__ out)
{
    __shared__ float tA[32][33];
    __shared__ float tB[32][33];
    const int b  = blockIdx.z;
    const int i0 = blockIdx.y * 32, j0 = blockIdx.x * 32;
    const int tx = threadIdx.x & 31, ty = threadIdx.x >> 5;
    const float* Cb = g_C + (size_t)b * LL * LL;

    #pragma unroll
    for (int r = 0; r < 4; ++r) {
        int row = ty + r * 8;
        int gi = i0 + row, gj = j0 + tx;
        tA[row][tx] = (gi < LL && gj < LL) ? Cb[gi * LL + gj] : 0.f;
        int hi = j0 + row, hj = i0 + tx;
        tB[row][tx] = (hi < LL && hj < LL) ? Cb[hi * LL + hj] : 0.f;
    }
    __syncthreads();

    float* Ob = out + (size_t)b * LL * LL;
    #pragma unroll
    for (int r = 0; r < 4; ++r) {
        int row = ty + r * 8;
        int gi = i0 + row, gj = j0 + tx;
        if (gi < LL && gj < LL)
            Ob[gi * LL + gj] = 0.5f * (tA[row][tx] + tB[tx][row]);
    }
}

// ---------------------------------------------------------------------------
extern "C" void kernel_launch(void* const* d_in, const int* in_sizes, int n_in,
                              void* d_out, int out_size)
{
    (void)in_sizes; (void)n_in; (void)out_size;
    const float* x     = (const float*)d_in[0];
    const float* W_bil = (const float*)d_in[1];
    const float* b_bil = (const float*)d_in[2];
    const float* ln_g  = (const float*)d_in[3];
    const float* ln_b  = (const float*)d_in[4];
    const float* W1    = (const float*)d_in[5];
    const float* b1    = (const float*)d_in[6];
    const float* w2    = (const float*)d_in[7];
    const float* b2    = (const float*)d_in[8];
    float* out = (float*)d_out;

    cudaFuncSetAttribute(k1_tmp,   cudaFuncAttributeMaxDynamicSharedMemorySize, K1_SMEM);
    cudaFuncSetAttribute(k2_fused, cudaFuncAttributeMaxDynamicSharedMemorySize, K2_SMEM);

    k0_transpose<<<128, 256>>>(W_bil);
    k0x_convert<<<(BB * 512 * 64 + 255) / 256, 256>>>(x);
    k0w_fold<<<128, 128>>>(W1, ln_g, ln_b, b1);
    dim3 g1(128, (NBI + 127) / 128);   // 128 x 7
    k1_tmp<<<g1, 256, K1_SMEM>>>();
    k2_fused<<<NBI, 256, K2_SMEM>>>(b_bil, w2, b2);

    dim3 g3((LL + 31) / 32, (LL + 31) / 32, BB);   // 13 x 13 x 2
    k3_sym<<<g3, 256>>>(out);
}

// round 15
// speedup vs baseline: 1.1319x; 1.0002x over previous
#include <cuda_runtime.h>
#include <cuda_fp16.h>
#include <math.h>
#include <stdint.h>

#define BB 2
#define LL 401
#define DD 128
#define NBI (BB*LL)   // 802
#define HP 68         // smem row pitch in half2 (136 halfs, 272 B)

__device__ __half g_tmp_h[(size_t)NBI * DD * DD];             // 26.3 MB tmp[b,i,k,e] fp16
__device__ __align__(16) __half2 g_WbT[(size_t)DD * DD * 64]; // 4 MB: [k][e][d-pairs]
__device__ __align__(16) __half  g_x_h[(size_t)BB * 512 * DD];// padded fp16 x: [b][512][128]
__device__ __align__(16) __half  g_W1p[(size_t)DD * DD];      // W1[e][d]*ln_g[d] fp16
__device__ float  g_b1p[DD];                                  // b1 + ln_b @ W1^T
__device__ float  g_C[(size_t)BB * LL * LL];

// ---------------------------------------------------------------------------
__device__ __forceinline__ void mma_f16(float c[4],
                                        uint32_t a0, uint32_t a1, uint32_t a2, uint32_t a3,
                                        uint32_t b0, uint32_t b1)
{
    asm volatile(
        "mma.sync.aligned.m16n8k16.row.col.f32.f16.f16.f32 "
        "{%0,%1,%2,%3}, {%4,%5,%6,%7}, {%8,%9}, {%0,%1,%2,%3};"
        : "+f"(c[0]), "+f"(c[1]), "+f"(c[2]), "+f"(c[3])
        : "r"(a0), "r"(a1), "r"(a2), "r"(a3), "r"(b0), "r"(b1));
}
__device__ __forceinline__ void ldsm4(uint32_t r[4], uint32_t addr)
{
    asm volatile("ldmatrix.sync.aligned.m8n8.x4.shared.b16 {%0,%1,%2,%3}, [%4];"
                 : "=r"(r[0]), "=r"(r[1]), "=r"(r[2]), "=r"(r[3]) : "r"(addr));
}
__device__ __forceinline__ void cpa16(uint32_t dst, const void* src)
{
    asm volatile("cp.async.cg.shared.global [%0], [%1], 16;" :: "r"(dst), "l"(src));
}
__device__ __forceinline__ void cp_commit()
{
    asm volatile("cp.async.commit_group;" ::: "memory");
}
template <int N>
__device__ __forceinline__ void cp_wait()
{
    asm volatile("cp.async.wait_group %0;" :: "n"(N) : "memory");
}

// Branch-free GELU without the 0.5 (folded into w2): v*(1+erf(v/sqrt2)).
// A&S 7.1.25 3-term erf (|err| <= 2.5e-5), rcp.approx + expf.
__device__ __forceinline__ float gelu2x(float v)
{
    float z   = v * 0.70710678118654752f;
    float az  = fabsf(z);
    float den = fmaf(0.47047f, az, 1.0f);
    float t;
    asm("rcp.approx.f32 %0, %1;" : "=f"(t) : "f"(den));
    float e = __expf(-z * z);
    float p = fmaf(0.7478556f, t, -0.0958798f);
    p = fmaf(p, t, 0.3480242f);
    p = p * t;
    float erfa = fmaf(-p, e, 1.0f);
    float erfv = copysignf(erfa, z);
    return v * (1.0f + erfv);
}

// ---------------------------------------------------------------------------
// Kernel 0: one-time transpose W_bil[k][d][e] (fp32) -> g_WbT[k][e][d-pairs] (fp16)
// ---------------------------------------------------------------------------
__global__ __launch_bounds__(256, 2) void k0_transpose(const float* __restrict__ Wb)
{
    __shared__ __half Sg[128 * 130];
    const int k   = blockIdx.x;
    const int tid = threadIdx.x;
    const float* Wk = Wb + (size_t)k * DD * DD;

    #pragma unroll
    for (int s = 0; s < 16; ++s) {
        int v = tid + (s << 8);
        int d = v >> 5, e4 = (v & 31) << 2;
        float4 w = *(const float4*)&Wk[d * DD + e4];
        __half2* dst = (__half2*)&Sg[d * 130 + e4];
        dst[0] = __floats2half2_rn(w.x, w.y);
        dst[1] = __floats2half2_rn(w.z, w.w);
    }
    __syncthreads();

    __half2* out = g_WbT + (size_t)k * (DD * 64);
    #pragma unroll
    for (int s = 0; s < 32; ++s) {
        int v = tid + (s << 8);
        int e = v >> 6, d2 = v & 63;
        __half lo = Sg[(2 * d2) * 130 + e];
        __half hi = Sg[(2 * d2 + 1) * 130 + e];
        out[e * 64 + d2] = __halves2half2(lo, hi);
    }
}

// ---------------------------------------------------------------------------
// Kernel 0x: convert x (fp32) -> g_x_h fp16, padded to 512 rows per b.
// ---------------------------------------------------------------------------
__global__ __launch_bounds__(256) void k0x_convert(const float* __restrict__ x)
{
    int idx = blockIdx.x * 256 + threadIdx.x;
    if (idx >= BB * 512 * 64) return;
    int b   = idx >> 15;
    int rem = idx & 32767;
    int r   = rem >> 6, c2 = rem & 63;
    __half2 h;
    if (r < LL) {
        const float* sp = &x[((size_t)(b * LL + r)) * DD + c2 * 2];
        h = __floats2half2_rn(sp[0], sp[1]);
    } else {
        h = __floats2half2_rn(0.f, 0.f);
    }
    *(__half2*)&g_x_h[((size_t)(b * 512 + r)) * DD + c2 * 2] = h;
}

// ---------------------------------------------------------------------------
// Kernel 0w (parallel): fold LN affine into W1.
// ---------------------------------------------------------------------------
__global__ __launch_bounds__(128) void k0w_fold(const float* __restrict__ W1,
                                                const float* __restrict__ ln_g,
                                                const float* __restrict__ ln_b,
                                                const float* __restrict__ b1)
{
    __shared__ float red[4];
    const int e = blockIdx.x, d = threadIdx.x;
    float w = W1[e * DD + d];
    g_W1p[e * DD + d] = __float2half_rn(w * ln_g[d]);
    float v = ln_b[d] * w;
    #pragma unroll
    for (int off = 16; off > 0; off >>= 1)
        v += __shfl_xor_sync(0xffffffffu, v, off);
    if ((d & 31) == 0) red[d >> 5] = v;
    __syncthreads();
    if (d == 0)
        g_b1p[e] = b1[e] + red[0] + red[1] + red[2] + red[3];
}

// ---------------------------------------------------------------------------
// Kernel 1 (fp16 mma + ldmatrix + cp.async pipeline): 4 k-slices per CTA.
// Grid (32, 7): kg covers k = 4*kg .. 4*kg+3; x loaded ONCE per CTA;
// Wt double-buffered via cp.async (next slice streams during current mainloop).
// ---------------------------------------------------------------------------
#define K1_XS  0u
#define K1_WA  34816u
#define K1_WB  69632u
#define K1_SMEM 104448u

__global__ __launch_bounds__(256, 2) void k1_tmp()
{
    extern __shared__ char smc[];
    __half2* Xs = (__half2*)(smc + K1_XS);

    const int kg  = blockIdx.x;          // 0..31
    const int bi0 = blockIdx.y * 128;
    const int tid = threadIdx.x, tx = tid & 31, wid = tid >> 5;
    const int wj  = wid & 3, wk = wid >> 2;
    const int g   = tx >> 2, c = tx & 3;
    const int arow = wj * 32, bcol = wk * 64;

    const uint32_t sb  = (uint32_t)__cvta_generic_to_shared(smc);
    const uint32_t sbX = sb + K1_XS;
    const uint32_t wbase[2] = {sb + K1_WA, sb + K1_WB};

    // ---- x rows -> Xs (once) ----
    #pragma unroll
    for (int s = 0; s < 8; ++s) {
        int v = tid + (s << 8);
        int row = v >> 4, seg = v & 15;
        int bi = bi0 + row;
        int bb_ = (bi >= LL) ? 1 : 0;
        int r = bi - bb_ * LL;
        uint4 t = *(const uint4*)&g_x_h[((size_t)(bb_ * 512 + r)) * DD + seg * 8];
        *(uint4*)(smc + K1_XS + row * 272 + seg * 16) = t;
    }
    // ---- prefetch Wt[k0] into buffer A ----
    {
        const __half2* Wsrc = g_WbT + (size_t)(kg * 4) * (DD * 64);
        #pragma unroll
        for (int s = 0; s < 8; ++s) {
            int v = tid + (s << 8);
            int row = v >> 4, u = (v & 15) << 2;     // half2 index
            cpa16(wbase[0] + row * 272 + u * 4, &Wsrc[row * 64 + u]);
        }
        cp_commit();
    }

    uint32_t aAddr[2], bOff[4];
    #pragma unroll
    for (int mf = 0; mf < 2; ++mf) {
        int row = arow + mf * 16 + (tx & 7) + ((tx & 8) ? 8 : 0);
        aAddr[mf] = sbX + row * 272 + ((tx & 16) ? 16 : 0);
    }
    #pragma unroll
    for (int p = 0; p < 4; ++p) {
        int row = bcol + p * 16 + (tx & 7) + ((tx & 16) ? 8 : 0);
        bOff[p] = row * 272 + ((tx & 8) ? 16 : 0);
    }

    #pragma unroll 1
    for (int kk = 0; kk < 4; ++kk) {
        const int k = kg * 4 + kk;
        // prefetch next slice into the other buffer
        if (kk < 3) {
            const __half2* Wsrc = g_WbT + (size_t)(k + 1) * (DD * 64);
            uint32_t dstb = wbase[(kk + 1) & 1];
            #pragma unroll
            for (int s = 0; s < 8; ++s) {
                int v = tid + (s << 8);
                int row = v >> 4, u = (v & 15) << 2;
                cpa16(dstb + row * 272 + u * 4, &Wsrc[row * 64 + u]);
            }
            cp_commit();
            cp_wait<1>();       // current buffer complete; next still in flight
        } else {
            cp_wait<0>();
        }
        __syncthreads();

        const uint32_t wb = wbase[kk & 1];
        float acc[2][8][4];
        #pragma unroll
        for (int mf = 0; mf < 2; ++mf)
            #pragma unroll
            for (int nt = 0; nt < 8; ++nt)
                #pragma unroll
                for (int u = 0; u < 4; ++u) acc[mf][nt][u] = 0.0f;

        #pragma unroll
        for (int kc = 0; kc < 8; ++kc) {
            int ko = kc * 32;
            uint32_t a0[4], a1[4];
            ldsm4(a0, aAddr[0] + ko);
            ldsm4(a1, aAddr[1] + ko);
            #pragma unroll
            for (int p = 0; p < 4; ++p) {
                uint32_t bb[4];
                ldsm4(bb, wb + bOff[p] + ko);
                mma_f16(acc[0][2 * p],     a0[0], a0[1], a0[2], a0[3], bb[0], bb[1]);
                mma_f16(acc[1][2 * p],     a1[0], a1[1], a1[2], a1[3], bb[0], bb[1]);
                mma_f16(acc[0][2 * p + 1], a0[0], a0[1], a0[2], a0[3], bb[2], bb[3]);
                mma_f16(acc[1][2 * p + 1], a1[0], a1[1], a1[2], a1[3], bb[2], bb[3]);
            }
        }

        #pragma unroll
        for (int mf = 0; mf < 2; ++mf)
            #pragma unroll
            for (int nt = 0; nt < 8; ++nt) {
                int r0  = bi0 + arow + mf * 16 + g;
                int col = bcol + nt * 8 + 2 * c;
                if (r0 < NBI)
                    *(__half2*)&g_tmp_h[(size_t)r0 * (DD * DD) + k * DD + col] =
                        __floats2half2_rn(acc[mf][nt][0], acc[mf][nt][1]);
                int r1 = r0 + 8;
                if (r1 < NBI)
                    *(__half2*)&g_tmp_h[(size_t)r1 * (DD * DD) + k * DD + col] =
                        __floats2half2_rn(acc[mf][nt][2], acc[mf][nt][3]);
            }
        __syncthreads();   // all reads of buf[kk&1] done before it is overwritten
    }
}

// ---------------------------------------------------------------------------
// Kernel 2 (fully warp-synchronous): per (b,i) CTA. Each warp owns 16 j-rows
// x 128 cols end-to-end; no named barriers, no smem reductions.
// ---------------------------------------------------------------------------
#define K2_TS 0u
#define K2_WS 34816u
#define K2_XS 69632u
#define K2_CV 104448u        // 384 floats: bbs, b1s, w2s
#define K2_SMEM 106240u

__global__ __launch_bounds__(256, 2) void k2_fused(
    const float* __restrict__ b_bil, const float* __restrict__ w2,
    const float* __restrict__ b2)
{
    extern __shared__ char smc[];
    __half2* Xs  = (__half2*)(smc + K2_XS);
    float* cv  = (float*)(smc + K2_CV);
    float* bbs = cv; float* b1s = cv + 128; float* w2s = cv + 256;

    const int bi  = blockIdx.x;
    const int b   = bi / LL;
    const int tid = threadIdx.x, tx = tid & 31, wid = tid >> 5;
    const int g   = tx >> 2, c = tx & 3;
    const int arow = wid * 16;

    // Ts: raw fp16 copy of tmp_i.  W1s: raw fp16 copy of pre-folded W1'.
    const __half* tp = g_tmp_h + (size_t)bi * DD * DD;
    #pragma unroll
    for (int s = 0; s < 8; ++s) {
        int v = tid + (s << 8);
        int row = v >> 4, seg = (v & 15) << 3;
        uint4 tv = *(const uint4*)&tp[row * DD + seg];
        *(uint4*)(smc + K2_TS + row * 272 + seg * 2) = tv;
        uint4 wv = *(const uint4*)&g_W1p[row * DD + seg];
        *(uint4*)(smc + K2_WS + row * 272 + seg * 2) = wv;
    }
    if (tid < 128) {
        bbs[tid] = b_bil[tid];
        b1s[tid] = g_b1p[tid];
        w2s[tid] = 0.5f * w2[tid];   // GELU 0.5 folded
    }
    const float b2v = b2[0];
    const __half* xh = g_x_h + (size_t)b * 512 * DD;
    float* Crow = g_C + (size_t)bi * LL;

    const uint32_t sb  = (uint32_t)__cvta_generic_to_shared(smc);
    const uint32_t sbX = sb + K2_XS, sbT = sb + K2_TS, sbW = sb + K2_WS;

    const uint32_t aAddr =
        sbX + (arow + (tx & 7) + ((tx & 8) ? 8 : 0)) * 272 + ((tx & 16) ? 16 : 0);
    uint32_t bOff[8];
    #pragma unroll
    for (int p = 0; p < 8; ++p) {
        int row = p * 16 + (tx & 7) + ((tx & 16) ? 8 : 0);
        bOff[p] = row * 272 + ((tx & 8) ? 16 : 0);
    }
    __syncthreads();   // Ts/W1s/constants visible; the ONLY CTA-wide sync

    #pragma unroll 1
    for (int t = 0; t < 4; ++t) {
        const int j0 = t * 128;
        const int mrows = (t == 3) ? 32 : 128;
        if (arow >= mrows) continue;   // whole warp skips together

        // ---- Warp loads its own 16 X rows (raw fp16, 8 uint4/thread) ----
        #pragma unroll
        for (int s = 0; s < 8; ++s) {
            int u = tx + (s << 5);
            int row = arow + (u >> 4), seg = u & 15;
            uint4 tv = *(const uint4*)&xh[((size_t)(j0 + row)) * DD + seg * 8];
            *(uint4*)(smc + K2_XS + row * 272 + seg * 16) = tv;
        }
        __syncwarp();

        // ---- Phase A: pair = X @ Ts^T (warp tile 16m x 128n) ----
        float acc[16][4];
        #pragma unroll
        for (int nt = 0; nt < 16; ++nt)
            #pragma unroll
            for (int u = 0; u < 4; ++u) acc[nt][u] = 0.0f;

        #pragma unroll
        for (int kc = 0; kc < 8; ++kc) {
            int ko = kc * 32;
            uint32_t a0[4];
            ldsm4(a0, aAddr + ko);
            #pragma unroll
            for (int p = 0; p < 8; ++p) {
                uint32_t bb[4];
                ldsm4(bb, sbT + bOff[p] + ko);
                mma_f16(acc[2 * p],     a0[0], a0[1], a0[2], a0[3], bb[0], bb[1]);
                mma_f16(acc[2 * p + 1], a0[0], a0[1], a0[2], a0[3], bb[2], bb[3]);
            }
        }

        // ---- LN stats: thread holds ALL 128 cols of its 2 rows ----
        float s1a = 0.f, s2a = 0.f, s1b = 0.f, s2b = 0.f;
        #pragma unroll
        for (int nt = 0; nt < 16; ++nt) {
            int col = nt * 8 + 2 * c;
            float bb0 = bbs[col], bb1 = bbs[col + 1];
            acc[nt][0] += bb0; acc[nt][1] += bb1;
            acc[nt][2] += bb0; acc[nt][3] += bb1;
            s1a += acc[nt][0] + acc[nt][1];
            s2a += acc[nt][0] * acc[nt][0] + acc[nt][1] * acc[nt][1];
            s1b += acc[nt][2] + acc[nt][3];
            s2b += acc[nt][2] * acc[nt][2] + acc[nt][3] * acc[nt][3];
        }
        #pragma unroll
        for (int off = 1; off <= 2; off <<= 1) {
            s1a += __shfl_xor_sync(0xffffffffu, s1a, off);
            s2a += __shfl_xor_sync(0xffffffffu, s2a, off);
            s1b += __shfl_xor_sync(0xffffffffu, s1b, off);
            s2b += __shfl_xor_sync(0xffffffffu, s2b, off);
        }
        float mua = s1a * (1.0f / 128.0f);
        float rsa = rsqrtf(s2a * (1.0f / 128.0f) - mua * mua + 1e-5f);
        float mub = s1b * (1.0f / 128.0f);
        float rsb = rsqrtf(s2b * (1.0f / 128.0f) - mub * mub + 1e-5f);

        // ---- Write H = (pair - mu)*rs (fp16) into own Xs rows ----
        #pragma unroll
        for (int nt = 0; nt < 16; ++nt) {
            int col = nt * 8 + 2 * c;
            int h2i = (col >> 1);
            Xs[(arow + g) * HP + h2i] = __floats2half2_rn(
                (acc[nt][0] - mua) * rsa, (acc[nt][1] - mua) * rsa);
            Xs[(arow + 8 + g) * HP + h2i] = __floats2half2_rn(
                (acc[nt][2] - mub) * rsb, (acc[nt][3] - mub) * rsb);
        }
        __syncwarp();

        // ---- Phase B: o = H @ W1'^T ----
        #pragma unroll
        for (int nt = 0; nt < 16; ++nt)
            #pragma unroll
            for (int u = 0; u < 4; ++u) acc[nt][u] = 0.0f;

        #pragma unroll
        for (int kc = 0; kc < 8; ++kc) {
            int ko = kc * 32;
            uint32_t a0[4];
            ldsm4(a0, aAddr + ko);
            #pragma unroll
            for (int p = 0; p < 8; ++p) {
                uint32_t bb[4];
                ldsm4(bb, sbW + bOff[p] + ko);
                mma_f16(acc[2 * p],     a0[0], a0[1], a0[2], a0[3], bb[0], bb[1]);
                mma_f16(acc[2 * p + 1], a0[0], a0[1], a0[2], a0[3], bb[2], bb[3]);
            }
        }

        // ---- Epilogue: bias, GELU, full-row dot -> direct C write ----
        float ta = 0.f, tb = 0.f;
        #pragma unroll
        for (int nt = 0; nt < 16; ++nt) {
            int col = nt * 8 + 2 * c;
            float c0 = b1s[col], c1 = b1s[col + 1];
            float w0 = w2s[col], w1 = w2s[col + 1];
            ta += gelu2x(acc[nt][0] + c0) * w0 + gelu2x(acc[nt][1] + c1) * w1;
            tb += gelu2x(acc[nt][2] + c0) * w0 + gelu2x(acc[nt][3] + c1) * w1;
        }
        #pragma unroll
        for (int off = 1; off <= 2; off <<= 1) {
            ta += __shfl_xor_sync(0xffffffffu, ta, off);
            tb += __shfl_xor_sync(0xffffffffu, tb, off);
        }
        if (c == 0) {
            int ja = j0 + arow + g;
            int jb = ja + 8;
            if (ja < LL) Crow[ja] = ta + b2v;
            if (jb < LL) Crow[jb] = tb + b2v;
        }
    }
}

// ---------------------------------------------------------------------------
// Kernel 3: out[b,i,j] = 0.5*(C[b,i,j] + C[b,j,i]) with smem tile transpose.
// ---------------------------------------------------------------------------
__global__ __launch_bounds__(256) void k3_sym(float* __restrict__ out)
{
    __shared__ float tA[32][33];
    __shared__ float tB[32][33];
    const int b  = blockIdx.z;
    const int i0 = blockIdx.y * 32, j0 = blockIdx.x * 32;
    const int tx = threadIdx.x & 31, ty = threadIdx.x >> 5;
    const float* Cb = g_C + (size_t)b * LL * LL;

    #pragma unroll
    for (int r = 0; r < 4; ++r) {
        int row = ty + r * 8;
        int gi = i0 + row, gj = j0 + tx;
        tA[row][tx] = (gi < LL && gj < LL) ? Cb[gi * LL + gj] : 0.f;
        int hi = j0 + row, hj = i0 + tx;
        tB[row][tx] = (hi < LL && hj < LL) ? Cb[hi * LL + hj] : 0.f;
    }
    __syncthreads();

    float* Ob = out + (size_t)b * LL * LL;
    #pragma unroll
    for (int r = 0; r < 4; ++r) {
        int row = ty + r * 8;
        int gi = i0 + row, gj = j0 + tx;
        if (gi < LL && gj < LL)
            Ob[gi * LL + gj] = 0.5f * (tA[row][tx] + tB[tx][row]);
    }
}

// ---------------------------------------------------------------------------
extern "C" void kernel_launch(void* const* d_in, const int* in_sizes, int n_in,
                              void* d_out, int out_size)
{
    (void)in_sizes; (void)n_in; (void)out_size;
    const float* x     = (const float*)d_in[0];
    const float* W_bil = (const float*)d_in[1];
    const float* b_bil = (const float*)d_in[2];
    const float* ln_g  = (const float*)d_in[3];
    const float* ln_b  = (const float*)d_in[4];
    const float* W1    = (const float*)d_in[5];
    const float* b1    = (const float*)d_in[6];
    const float* w2    = (const float*)d_in[7];
    const float* b2    = (const float*)d_in[8];
    float* out = (float*)d_out;

    cudaFuncSetAttribute(k1_tmp,   cudaFuncAttributeMaxDynamicSharedMemorySize, K1_SMEM);
    cudaFuncSetAttribute(k2_fused, cudaFuncAttributeMaxDynamicSharedMemorySize, K2_SMEM);

    k0_transpose<<<128, 256>>>(W_bil);
    k0x_convert<<<(BB * 512 * 64 + 255) / 256, 256>>>(x);
    k0w_fold<<<128, 128>>>(W1, ln_g, ln_b, b1);
    dim3 g1(32, (NBI + 127) / 128);   // 32 x 7, 4 k-slices per CTA
    k1_tmp<<<g1, 256, K1_SMEM>>>();
    k2_fused<<<NBI, 256, K2_SMEM>>>(b_bil, w2, b2);

    dim3 g3((LL + 31) / 32, (LL + 31) / 32, BB);   // 13 x 13 x 2
    k3_sym<<<g3, 256>>>(out);
}

// round 16
// speedup vs baseline: 1.1661x; 1.0302x over previous
#include <cuda_runtime.h>
#include <cuda_fp16.h>
#include <math.h>
#include <stdint.h>

#define BB 2
#define LL 401
#define DD 128
#define NBI (BB*LL)   // 802
#define HP 68         // smem row pitch in half2 (136 halfs, 272 B)

__device__ __half g_tmp_h[(size_t)NBI * DD * DD];             // 26.3 MB tmp[b,i,k,e] fp16
__device__ __align__(16) __half2 g_WbT[(size_t)DD * DD * 64]; // 4 MB: [k][e][d-pairs]
__device__ __align__(16) __half  g_x_h[(size_t)BB * 512 * DD];// padded fp16 x: [b][512][128]
__device__ __align__(16) __half  g_W1p[(size_t)DD * DD];      // W1[e][d]*ln_g[d] fp16
__device__ float  g_b1p[DD];                                  // b1 + ln_b @ W1^T
__device__ float  g_C[(size_t)BB * LL * LL];

// ---------------------------------------------------------------------------
__device__ __forceinline__ void mma_f16(float c[4],
                                        uint32_t a0, uint32_t a1, uint32_t a2, uint32_t a3,
                                        uint32_t b0, uint32_t b1)
{
    asm volatile(
        "mma.sync.aligned.m16n8k16.row.col.f32.f16.f16.f32 "
        "{%0,%1,%2,%3}, {%4,%5,%6,%7}, {%8,%9}, {%0,%1,%2,%3};"
        : "+f"(c[0]), "+f"(c[1]), "+f"(c[2]), "+f"(c[3])
        : "r"(a0), "r"(a1), "r"(a2), "r"(a3), "r"(b0), "r"(b1));
}
__device__ __forceinline__ void ldsm4(uint32_t r[4], uint32_t addr)
{
    asm volatile("ldmatrix.sync.aligned.m8n8.x4.shared.b16 {%0,%1,%2,%3}, [%4];"
                 : "=r"(r[0]), "=r"(r[1]), "=r"(r[2]), "=r"(r[3]) : "r"(addr));
}

// Branch-free GELU without the 0.5 (folded into w2): v*(1+erf(v/sqrt2)).
// A&S 7.1.25 3-term erf (|err| <= 2.5e-5), rcp.approx + expf.
__device__ __forceinline__ float gelu2x(float v)
{
    float z   = v * 0.70710678118654752f;
    float az  = fabsf(z);
    float den = fmaf(0.47047f, az, 1.0f);
    float t;
    asm("rcp.approx.f32 %0, %1;" : "=f"(t) : "f"(den));
    float e = __expf(-z * z);
    float p = fmaf(0.7478556f, t, -0.0958798f);
    p = fmaf(p, t, 0.3480242f);
    p = p * t;
    float erfa = fmaf(-p, e, 1.0f);
    float erfv = copysignf(erfa, z);
    return v * (1.0f + erfv);
}

// ---------------------------------------------------------------------------
// Kernel 0: one-time transpose W_bil[k][d][e] (fp32) -> g_WbT[k][e][d-pairs] (fp16)
// ---------------------------------------------------------------------------
__global__ __launch_bounds__(256, 2) void k0_transpose(const float* __restrict__ Wb)
{
    __shared__ __half Sg[128 * 130];
    const int k   = blockIdx.x;
    const int tid = threadIdx.x;
    const float* Wk = Wb + (size_t)k * DD * DD;

    #pragma unroll
    for (int s = 0; s < 16; ++s) {
        int v = tid + (s << 8);
        int d = v >> 5, e4 = (v & 31) << 2;
        float4 w = *(const float4*)&Wk[d * DD + e4];
        __half2* dst = (__half2*)&Sg[d * 130 + e4];
        dst[0] = __floats2half2_rn(w.x, w.y);
        dst[1] = __floats2half2_rn(w.z, w.w);
    }
    __syncthreads();

    __half2* out = g_WbT + (size_t)k * (DD * 64);
    #pragma unroll
    for (int s = 0; s < 32; ++s) {
        int v = tid + (s << 8);
        int e = v >> 6, d2 = v & 63;
        __half lo = Sg[(2 * d2) * 130 + e];
        __half hi = Sg[(2 * d2 + 1) * 130 + e];
        out[e * 64 + d2] = __halves2half2(lo, hi);
    }
}

// ---------------------------------------------------------------------------
// Kernel 0x: convert x (fp32) -> g_x_h fp16, padded to 512 rows per b.
// ---------------------------------------------------------------------------
__global__ __launch_bounds__(256) void k0x_convert(const float* __restrict__ x)
{
    int idx = blockIdx.x * 256 + threadIdx.x;
    if (idx >= BB * 512 * 64) return;
    int b   = idx >> 15;
    int rem = idx & 32767;
    int r   = rem >> 6, c2 = rem & 63;
    __half2 h;
    if (r < LL) {
        const float* sp = &x[((size_t)(b * LL + r)) * DD + c2 * 2];
        h = __floats2half2_rn(sp[0], sp[1]);
    } else {
        h = __floats2half2_rn(0.f, 0.f);
    }
    *(__half2*)&g_x_h[((size_t)(b * 512 + r)) * DD + c2 * 2] = h;
}

// ---------------------------------------------------------------------------
// Kernel 0w (parallel): fold LN affine into W1.
// ---------------------------------------------------------------------------
__global__ __launch_bounds__(128) void k0w_fold(const float* __restrict__ W1,
                                                const float* __restrict__ ln_g,
                                                const float* __restrict__ ln_b,
                                                const float* __restrict__ b1)
{
    __shared__ float red[4];
    const int e = blockIdx.x, d = threadIdx.x;
    float w = W1[e * DD + d];
    g_W1p[e * DD + d] = __float2half_rn(w * ln_g[d]);
    float v = ln_b[d] * w;
    #pragma unroll
    for (int off = 16; off > 0; off >>= 1)
        v += __shfl_xor_sync(0xffffffffu, v, off);
    if ((d & 31) == 0) red[d >> 5] = v;
    __syncthreads();
    if (d == 0)
        g_b1p[e] = b1[e] + red[0] + red[1] + red[2] + red[3];
}

// ---------------------------------------------------------------------------
// Kernel 1 (round-14 version, fp16 mma + ldmatrix): one k-slice per CTA.
// tmp[bi][k][e] = sum_d x[bi][d]*W_bil[k][d][e]
// ---------------------------------------------------------------------------
#define K1_XS 0u
#define K1_WT 34816u
#define K1_SMEM 69632u

__global__ __launch_bounds__(256, 2) void k1_tmp()
{
    extern __shared__ char smc[];
    __half2* Xs = (__half2*)(smc + K1_XS);
    __half2* Wt = (__half2*)(smc + K1_WT);

    const int k   = blockIdx.x;
    const int bi0 = blockIdx.y * 128;
    const int tid = threadIdx.x, tx = tid & 31, wid = tid >> 5;
    const int wj  = wid & 3, wk = wid >> 2;
    const int g   = tx >> 2, c = tx & 3;
    const int arow = wj * 32, bcol = wk * 64;

    const __half2* Wsrc = g_WbT + (size_t)k * (DD * 64);
    #pragma unroll
    for (int s = 0; s < 8; ++s) {
        int v = tid + (s << 8);
        int row = v >> 4, u = (v & 15) << 2;
        uint4 t = *(const uint4*)&Wsrc[row * 64 + u];
        *(uint4*)&Wt[row * HP + u] = t;
    }
    #pragma unroll
    for (int s = 0; s < 8; ++s) {
        int v = tid + (s << 8);
        int row = v >> 4, seg = v & 15;
        int bi = bi0 + row;
        int bb_ = (bi >= LL) ? 1 : 0;
        int r = bi - bb_ * LL;
        uint4 t = *(const uint4*)&g_x_h[((size_t)(bb_ * 512 + r)) * DD + seg * 8];
        *(uint4*)((char*)Xs + row * 272 + seg * 16) = t;
    }
    __syncthreads();

    const uint32_t sb  = (uint32_t)__cvta_generic_to_shared(smc);
    const uint32_t sbX = sb + K1_XS, sbW = sb + K1_WT;

    uint32_t aAddr[2], bOff[4];
    #pragma unroll
    for (int mf = 0; mf < 2; ++mf) {
        int row = arow + mf * 16 + (tx & 7) + ((tx & 8) ? 8 : 0);
        aAddr[mf] = sbX + row * 272 + ((tx & 16) ? 16 : 0);
    }
    #pragma unroll
    for (int p = 0; p < 4; ++p) {
        int row = bcol + p * 16 + (tx & 7) + ((tx & 16) ? 8 : 0);
        bOff[p] = row * 272 + ((tx & 8) ? 16 : 0);
    }

    float acc[2][8][4];
    #pragma unroll
    for (int mf = 0; mf < 2; ++mf)
        #pragma unroll
        for (int nt = 0; nt < 8; ++nt)
            #pragma unroll
            for (int u = 0; u < 4; ++u) acc[mf][nt][u] = 0.0f;

    #pragma unroll
    for (int kc = 0; kc < 8; ++kc) {
        int ko = kc * 32;
        uint32_t a0[4], a1[4];
        ldsm4(a0, aAddr[0] + ko);
        ldsm4(a1, aAddr[1] + ko);
        #pragma unroll
        for (int p = 0; p < 4; ++p) {
            uint32_t bb[4];
            ldsm4(bb, sbW + bOff[p] + ko);
            mma_f16(acc[0][2 * p],     a0[0], a0[1], a0[2], a0[3], bb[0], bb[1]);
            mma_f16(acc[1][2 * p],     a1[0], a1[1], a1[2], a1[3], bb[0], bb[1]);
            mma_f16(acc[0][2 * p + 1], a0[0], a0[1], a0[2], a0[3], bb[2], bb[3]);
            mma_f16(acc[1][2 * p + 1], a1[0], a1[1], a1[2], a1[3], bb[2], bb[3]);
        }
    }

    #pragma unroll
    for (int mf = 0; mf < 2; ++mf)
        #pragma unroll
        for (int nt = 0; nt < 8; ++nt) {
            int r0  = bi0 + arow + mf * 16 + g;
            int col = bcol + nt * 8 + 2 * c;
            if (r0 < NBI)
                *(__half2*)&g_tmp_h[(size_t)r0 * (DD * DD) + k * DD + col] =
                    __floats2half2_rn(acc[mf][nt][0], acc[mf][nt][1]);
            int r1 = r0 + 8;
            if (r1 < NBI)
                *(__half2*)&g_tmp_h[(size_t)r1 * (DD * DD) + k * DD + col] =
                    __floats2half2_rn(acc[mf][nt][2], acc[mf][nt][3]);
        }
}

// ---------------------------------------------------------------------------
// Kernel 2 (fully warp-synchronous): per (b,i) CTA. Each warp owns 16 j-rows
// x 128 cols end-to-end; no named barriers, no smem reductions.
// ---------------------------------------------------------------------------
#define K2_TS 0u
#define K2_WS 34816u
#define K2_XS 69632u
#define K2_CV 104448u        // 384 floats: bbs, b1s, w2s
#define K2_SMEM 106240u

__global__ __launch_bounds__(256, 2) void k2_fused(
    const float* __restrict__ b_bil, const float* __restrict__ w2,
    const float* __restrict__ b2)
{
    extern __shared__ char smc[];
    __half2* Xs  = (__half2*)(smc + K2_XS);
    float* cv  = (float*)(smc + K2_CV);
    float* bbs = cv; float* b1s = cv + 128; float* w2s = cv + 256;

    const int bi  = blockIdx.x;
    const int b   = bi / LL;
    const int tid = threadIdx.x, tx = tid & 31, wid = tid >> 5;
    const int g   = tx >> 2, c = tx & 3;
    const int arow = wid * 16;

    // Ts: raw fp16 copy of tmp_i.  W1s: raw fp16 copy of pre-folded W1'.
    const __half* tp = g_tmp_h + (size_t)bi * DD * DD;
    #pragma unroll
    for (int s = 0; s < 8; ++s) {
        int v = tid + (s << 8);
        int row = v >> 4, seg = (v & 15) << 3;
        uint4 tv = *(const uint4*)&tp[row * DD + seg];
        *(uint4*)(smc + K2_TS + row * 272 + seg * 2) = tv;
        uint4 wv = *(const uint4*)&g_W1p[row * DD + seg];
        *(uint4*)(smc + K2_WS + row * 272 + seg * 2) = wv;
    }
    if (tid < 128) {
        bbs[tid] = b_bil[tid];
        b1s[tid] = g_b1p[tid];
        w2s[tid] = 0.5f * w2[tid];   // GELU 0.5 folded
    }
    const float b2v = b2[0];
    const __half* xh = g_x_h + (size_t)b * 512 * DD;
    float* Crow = g_C + (size_t)bi * LL;

    const uint32_t sb  = (uint32_t)__cvta_generic_to_shared(smc);
    const uint32_t sbX = sb + K2_XS, sbT = sb + K2_TS, sbW = sb + K2_WS;

    const uint32_t aAddr =
        sbX + (arow + (tx & 7) + ((tx & 8) ? 8 : 0)) * 272 + ((tx & 16) ? 16 : 0);
    uint32_t bOff[8];
    #pragma unroll
    for (int p = 0; p < 8; ++p) {
        int row = p * 16 + (tx & 7) + ((tx & 16) ? 8 : 0);
        bOff[p] = row * 272 + ((tx & 8) ? 16 : 0);
    }
    __syncthreads();   // Ts/W1s/constants visible; the ONLY CTA-wide sync

    #pragma unroll 1
    for (int t = 0; t < 4; ++t) {
        const int j0 = t * 128;
        const int mrows = (t == 3) ? 32 : 128;
        if (arow >= mrows) continue;   // whole warp skips together

        // ---- Warp loads its own 16 X rows (raw fp16, 8 uint4/thread) ----
        #pragma unroll
        for (int s = 0; s < 8; ++s) {
            int u = tx + (s << 5);
            int row = arow + (u >> 4), seg = u & 15;
            uint4 tv = *(const uint4*)&xh[((size_t)(j0 + row)) * DD + seg * 8];
            *(uint4*)(smc + K2_XS + row * 272 + seg * 16) = tv;
        }
        __syncwarp();

        // ---- Phase A: pair = X @ Ts^T (warp tile 16m x 128n) ----
        float acc[16][4];
        #pragma unroll
        for (int nt = 0; nt < 16; ++nt)
            #pragma unroll
            for (int u = 0; u < 4; ++u) acc[nt][u] = 0.0f;

        #pragma unroll
        for (int kc = 0; kc < 8; ++kc) {
            int ko = kc * 32;
            uint32_t a0[4];
            ldsm4(a0, aAddr + ko);
            #pragma unroll
            for (int p = 0; p < 8; ++p) {
                uint32_t bb[4];
                ldsm4(bb, sbT + bOff[p] + ko);
                mma_f16(acc[2 * p],     a0[0], a0[1], a0[2], a0[3], bb[0], bb[1]);
                mma_f16(acc[2 * p + 1], a0[0], a0[1], a0[2], a0[3], bb[2], bb[3]);
            }
        }

        // ---- LN stats: thread holds ALL 128 cols of its 2 rows ----
        float s1a = 0.f, s2a = 0.f, s1b = 0.f, s2b = 0.f;
        #pragma unroll
        for (int nt = 0; nt < 16; ++nt) {
            int col = nt * 8 + 2 * c;
            float bb0 = bbs[col], bb1 = bbs[col + 1];
            acc[nt][0] += bb0; acc[nt][1] += bb1;
            acc[nt][2] += bb0; acc[nt][3] += bb1;
            s1a += acc[nt][0] + acc[nt][1];
            s2a += acc[nt][0] * acc[nt][0] + acc[nt][1] * acc[nt][1];
            s1b += acc[nt][2] + acc[nt][3];
            s2b += acc[nt][2] * acc[nt][2] + acc[nt][3] * acc[nt][3];
        }
        #pragma unroll
        for (int off = 1; off <= 2; off <<= 1) {
            s1a += __shfl_xor_sync(0xffffffffu, s1a, off);
            s2a += __shfl_xor_sync(0xffffffffu, s2a, off);
            s1b += __shfl_xor_sync(0xffffffffu, s1b, off);
            s2b += __shfl_xor_sync(0xffffffffu, s2b, off);
        }
        float mua = s1a * (1.0f / 128.0f);
        float rsa = rsqrtf(s2a * (1.0f / 128.0f) - mua * mua + 1e-5f);
        float mub = s1b * (1.0f / 128.0f);
        float rsb = rsqrtf(s2b * (1.0f / 128.0f) - mub * mub + 1e-5f);

        // ---- Write H = (pair - mu)*rs (fp16) into own Xs rows ----
        #pragma unroll
        for (int nt = 0; nt < 16; ++nt) {
            int col = nt * 8 + 2 * c;
            int h2i = (col >> 1);
            Xs[(arow + g) * HP + h2i] = __floats2half2_rn(
                (acc[nt][0] - mua) * rsa, (acc[nt][1] - mua) * rsa);
            Xs[(arow + 8 + g) * HP + h2i] = __floats2half2_rn(
                (acc[nt][2] - mub) * rsb, (acc[nt][3] - mub) * rsb);
        }
        __syncwarp();

        // ---- Phase B: o = H @ W1'^T ----
        #pragma unroll
        for (int nt = 0; nt < 16; ++nt)
            #pragma unroll
            for (int u = 0; u < 4; ++u) acc[nt][u] = 0.0f;

        #pragma unroll
        for (int kc = 0; kc < 8; ++kc) {
            int ko = kc * 32;
            uint32_t a0[4];
            ldsm4(a0, aAddr + ko);
            #pragma unroll
            for (int p = 0; p < 8; ++p) {
                uint32_t bb[4];
                ldsm4(bb, sbW + bOff[p] + ko);
                mma_f16(acc[2 * p],     a0[0], a0[1], a0[2], a0[3], bb[0], bb[1]);
                mma_f16(acc[2 * p + 1], a0[0], a0[1], a0[2], a0[3], bb[2], bb[3]);
            }
        }

        // ---- Epilogue: bias, GELU, full-row dot -> direct C write ----
        float ta = 0.f, tb = 0.f;
        #pragma unroll
        for (int nt = 0; nt < 16; ++nt) {
            int col = nt * 8 + 2 * c;
            float c0 = b1s[col], c1 = b1s[col + 1];
            float w0 = w2s[col], w1 = w2s[col + 1];
            ta += gelu2x(acc[nt][0] + c0) * w0 + gelu2x(acc[nt][1] + c1) * w1;
            tb += gelu2x(acc[nt][2] + c0) * w0 + gelu2x(acc[nt][3] + c1) * w1;
        }
        #pragma unroll
        for (int off = 1; off <= 2; off <<= 1) {
            ta += __shfl_xor_sync(0xffffffffu, ta, off);
            tb += __shfl_xor_sync(0xffffffffu, tb, off);
        }
        if (c == 0) {
            int ja = j0 + arow + g;
            int jb = ja + 8;
            if (ja < LL) Crow[ja] = ta + b2v;
            if (jb < LL) Crow[jb] = tb + b2v;
        }
    }
}

// ---------------------------------------------------------------------------
// Kernel 3: out[b,i,j] = 0.5*(C[b,i,j] + C[b,j,i]) with smem tile transpose.
// ---------------------------------------------------------------------------
__global__ __launch_bounds__(256) void k3_sym(float* __restrict__ out)
{
    __shared__ float tA[32][33];
    __shared__ float tB[32][33];
    const int b  = blockIdx.z;
    const int i0 = blockIdx.y * 32, j0 = blockIdx.x * 32;
    const int tx = threadIdx.x & 31, ty = threadIdx.x >> 5;
    const float* Cb = g_C + (size_t)b * LL * LL;

    #pragma unroll
    for (int r = 0; r < 4; ++r) {
        int row = ty + r * 8;
        int gi = i0 + row, gj = j0 + tx;
        tA[row][tx] = (gi < LL && gj < LL) ? Cb[gi * LL + gj] : 0.f;
        int hi = j0 + row, hj = i0 + tx;
        tB[row][tx] = (hi < LL && hj < LL) ? Cb[hi * LL + hj] : 0.f;
    }
    __syncthreads();

    float* Ob = out + (size_t)b * LL * LL;
    #pragma unroll
    for (int r = 0; r < 4; ++r) {
        int row = ty + r * 8;
        int gi = i0 + row, gj = j0 + tx;
        if (gi < LL && gj < LL)
            Ob[gi * LL + gj] = 0.5f * (tA[row][tx] + tB[tx][row]);
    }
}

// ---------------------------------------------------------------------------
extern "C" void kernel_launch(void* const* d_in, const int* in_sizes, int n_in,
                              void* d_out, int out_size)
{
    (void)in_sizes; (void)n_in; (void)out_size;
    const float* x     = (const float*)d_in[0];
    const float* W_bil = (const float*)d_in[1];
    const float* b_bil = (const float*)d_in[2];
    const float* ln_g  = (const float*)d_in[3];
    const float* ln_b  = (const float*)d_in[4];
    const float* W1    = (const float*)d_in[5];
    const float* b1    = (const float*)d_in[6];
    const float* w2    = (const float*)d_in[7];
    const float* b2    = (const float*)d_in[8];
    float* out = (float*)d_out;

    cudaFuncSetAttribute(k1_tmp,   cudaFuncAttributeMaxDynamicSharedMemorySize, K1_SMEM);
    cudaFuncSetAttribute(k2_fused, cudaFuncAttributeMaxDynamicSharedMemorySize, K2_SMEM);

    k0_transpose<<<128, 256>>>(W_bil);
    k0x_convert<<<(BB * 512 * 64 + 255) / 256, 256>>>(x);
    k0w_fold<<<128, 128>>>(W1, ln_g, ln_b, b1);
    dim3 g1(128, (NBI + 127) / 128);   // 128 x 7, one k-slice per CTA
    k1_tmp<<<g1, 256, K1_SMEM>>>();
    k2_fused<<<NBI, 256, K2_SMEM>>>(b_bil, w2, b2);

    dim3 g3((LL + 31) / 32, (LL + 31) / 32, BB);   // 13 x 13 x 2
    k3_sym<<<g3, 256>>>(out);
}